// round 2
// baseline (speedup 1.0000x reference)
#include <cuda_runtime.h>
#include <math.h>

#define NBR 4
#define NL  3
#define BB  4
#define TT  1024
#define DIN 32
#define DM  128
#define DI  256
#define DS  16
#define DC  4
#define DTR 8
#define EMB 64
#define ROWS (NBR*BB*TT)   /* 16384 */
#define RPB  (BB*TT)       /* 4096  */
#define NBB  (NBR*BB)      /* 16    */
#define CHUNKS 16
#define CLEN (TT/CHUNKS)   /* 64    */
#define DBLW (DTR+2*DS)    /* 40    */
#define EPSV 1e-7f
#define MAXN 10.0f

// ---------------- scratch (static device memory; no allocs) ----------------
__device__ float g_h   [ROWS*DM];
__device__ float g_xz  [ROWS*2*DI];
__device__ float g_xc  [ROWS*DI];
__device__ float g_dbl [ROWS*DBLW];
__device__ float g_dt  [ROWS*DI];
__device__ float g_ym  [ROWS*DI];
__device__ float g_hend[CHUNKS*NBB*DI*DS];
__device__ float g_P   [CHUNKS*NBB*DI*DS];
__device__ float g_cry [CHUNKS*NBB*DI*DS];
__device__ float g_pool[NBB*DM];

__device__ __forceinline__ float warpsum(float v) {
#pragma unroll
    for (int o = 16; o > 0; o >>= 1) v += __shfl_xor_sync(0xffffffffu, v, o);
    return v;
}
__device__ __forceinline__ float siluf(float x) {
    return x / (1.f + __expf(-x));
}

// ---------------- input projection: h = x @ W_ip + b_ip --------------------
__global__ void k_inproj(const float* __restrict__ x0, const float* __restrict__ x1,
                         const float* __restrict__ x2, const float* __restrict__ x3,
                         const float* __restrict__ Wip, const float* __restrict__ bip) {
    int gid = blockIdx.x * blockDim.x + threadIdx.x;
    if (gid >= ROWS * DM) return;
    int dm = gid & (DM - 1);
    int m  = gid / DM;
    int nb = m / RPB;
    int r  = m - nb * RPB;
    const float* x = (nb == 0) ? x0 : (nb == 1) ? x1 : (nb == 2) ? x2 : x3;
    const float* xr = x + r * DIN;
    const float* w  = Wip + nb * DIN * DM + dm;
    float acc = bip[nb * DM + dm];
#pragma unroll
    for (int k = 0; k < DIN; k++) acc = fmaf(xr[k], w[k * DM], acc);
    g_h[gid] = acc;
}

// ---------------- tiled SGEMM: C[M,N] = A[M,K] @ W[K,N] per branch ---------
__global__ __launch_bounds__(256, 2)
void k_sgemm(const float* __restrict__ A, const float* __restrict__ W,
             float* __restrict__ C, int M, int N, int K,
             long sA, long sW, long sC) {
    A += (long)blockIdx.z * sA;
    W += (long)blockIdx.z * sW;
    C += (long)blockIdx.z * sC;
    __shared__ float As[8][128];
    __shared__ float Bs[8][128];
    int tid = threadIdx.x;
    int tx = tid & 15, ty = tid >> 4;
    int aRow = tid >> 1, aCol = (tid & 1) * 4;
    int bRow = tid >> 5, bCol = (tid & 31) * 4;
    int rowBase = blockIdx.y * 128;
    int colBase = blockIdx.x * 128;
    const float* Ap = A + (long)(rowBase + aRow) * K + aCol;
    float acc[8][8];
#pragma unroll
    for (int i = 0; i < 8; i++)
#pragma unroll
        for (int j = 0; j < 8; j++) acc[i][j] = 0.f;

    for (int k0 = 0; k0 < K; k0 += 8) {
        float4 av = *(const float4*)(Ap + k0);
        As[aCol + 0][aRow] = av.x;
        As[aCol + 1][aRow] = av.y;
        As[aCol + 2][aRow] = av.z;
        As[aCol + 3][aRow] = av.w;
        int gc = colBase + bCol;
        float4 bv = make_float4(0.f, 0.f, 0.f, 0.f);
        const float* wp = W + (long)(k0 + bRow) * N;
        if (gc + 3 < N) {
            bv = *(const float4*)(wp + gc);
        } else if (gc < N) {
            bv.x = wp[gc];
            if (gc + 1 < N) bv.y = wp[gc + 1];
            if (gc + 2 < N) bv.z = wp[gc + 2];
        }
        *(float4*)&Bs[bRow][bCol] = bv;
        __syncthreads();
#pragma unroll
        for (int kk = 0; kk < 8; kk++) {
            float ar[8], br[8];
            *(float4*)(ar)     = *(const float4*)&As[kk][ty * 8];
            *(float4*)(ar + 4) = *(const float4*)&As[kk][ty * 8 + 4];
            *(float4*)(br)     = *(const float4*)&Bs[kk][tx * 8];
            *(float4*)(br + 4) = *(const float4*)&Bs[kk][tx * 8 + 4];
#pragma unroll
            for (int i = 0; i < 8; i++)
#pragma unroll
                for (int j = 0; j < 8; j++) acc[i][j] = fmaf(ar[i], br[j], acc[i][j]);
        }
        __syncthreads();
    }
#pragma unroll
    for (int i = 0; i < 8; i++) {
        long row = rowBase + ty * 8 + i;
#pragma unroll
        for (int j = 0; j < 8; j++) {
            int col = colBase + tx * 8 + j;
            if (col < N) C[row * N + col] = acc[i][j];
        }
    }
}

// ---------------- causal depthwise conv (D_CONV=4) + SiLU ------------------
__global__ void k_conv(const float* __restrict__ cw, const float* __restrict__ cb, int l) {
    int gid = blockIdx.x * blockDim.x + threadIdx.x;
    if (gid >= ROWS * (DI / 4)) return;
    int q  = gid & 63;
    int m  = gid >> 6;
    int d0 = q * 4;
    int nb = m / RPB;
    int t  = m & (TT - 1);
    const float* cwp = cw + (((long)(nb * NL + l)) * DI + d0) * DC;
    float cwa[16];
    *(float4*)(cwa + 0)  = *(const float4*)(cwp + 0);
    *(float4*)(cwa + 4)  = *(const float4*)(cwp + 4);
    *(float4*)(cwa + 8)  = *(const float4*)(cwp + 8);
    *(float4*)(cwa + 12) = *(const float4*)(cwp + 12);
    const float* cbp = cb + (long)(nb * NL + l) * DI + d0;
    float a0 = cbp[0], a1 = cbp[1], a2 = cbp[2], a3 = cbp[3];
#pragma unroll
    for (int k = 0; k < DC; k++) {
        int tk = t + k - (DC - 1);
        if (tk >= 0) {
            const float* xp = g_xz + (long)(m + k - (DC - 1)) * (2 * DI) + d0;
            float4 xv = *(const float4*)xp;
            a0 = fmaf(xv.x, cwa[0 * DC + k], a0);
            a1 = fmaf(xv.y, cwa[1 * DC + k], a1);
            a2 = fmaf(xv.z, cwa[2 * DC + k], a2);
            a3 = fmaf(xv.w, cwa[3 * DC + k], a3);
        }
    }
    float4 o;
    o.x = siluf(a0); o.y = siluf(a1); o.z = siluf(a2); o.w = siluf(a3);
    *(float4*)(g_xc + (long)m * DI + d0) = o;
}

// ---------------- dt = softplus(dbl[:, :8] @ W_dt + b_dt) ------------------
__global__ void k_dt(const float* __restrict__ Wdt, const float* __restrict__ bdt, int l) {
    int gid = blockIdx.x * blockDim.x + threadIdx.x;
    if (gid >= ROWS * DI) return;
    int d = gid & (DI - 1);
    int m = gid >> 8;
    int nb = m / RPB;
    const float* db = g_dbl + (long)m * DBLW;
    const float* w  = Wdt + (long)(nb * NL + l) * DTR * DI + d;
    float u = bdt[(nb * NL + l) * DI + d];
#pragma unroll
    for (int r = 0; r < DTR; r++) u = fmaf(db[r], w[r * DI], u);
    float sp = (u > 20.f) ? u : log1pf(__expf(u));
    g_dt[gid] = sp;
}

// ---------------- scan pass 1: per-chunk local scan + dA product -----------
__global__ __launch_bounds__(256)
void k_scan1(const float* __restrict__ Alog, int l) {
    int c   = blockIdx.x;
    int nbb = blockIdx.y;
    int d   = threadIdx.x;
    int nb  = nbb >> 2;
    __shared__ float sB[CLEN][DS];
    int m0 = nbb * TT + c * CLEN;
    for (int i = d; i < CLEN * DS; i += 256) {
        int r = i >> 4, j = i & 15;
        sB[r][j] = g_dbl[(long)(m0 + r) * DBLW + DTR + j];
    }
    float a[DS];
    const float* Ap = Alog + ((long)(nb * NL + l) * DI + d) * DS;
#pragma unroll
    for (int s = 0; s < DS; s++) a[s] = -expf(Ap[s]);
    float A0 = a[0];
    bool ok = true;
#pragma unroll
    for (int s = 0; s < DS; s++)
        ok = ok && (fabsf(a[s] - (float)(s + 1) * A0) <= 1e-4f * fabsf(a[s]) + 1e-7f);
    __syncthreads();
    float h[DS], P[DS];
#pragma unroll
    for (int s = 0; s < DS; s++) { h[s] = 0.f; P[s] = 1.f; }
    if (ok) {
        for (int t = 0; t < CLEN; t++) {
            int mr = m0 + t;
            float dtv = g_dt[(long)mr * DI + d];
            float xcv = g_xc[(long)mr * DI + d];
            float w = dtv * xcv;
            float p = __expf(dtv * A0);
            float cum = 1.f;
#pragma unroll
            for (int s = 0; s < DS; s++) {
                cum *= p;
                h[s] = fmaf(cum, h[s], w * sB[t][s]);
                P[s] *= cum;
            }
        }
    } else {
        for (int t = 0; t < CLEN; t++) {
            int mr = m0 + t;
            float dtv = g_dt[(long)mr * DI + d];
            float xcv = g_xc[(long)mr * DI + d];
            float w = dtv * xcv;
#pragma unroll
            for (int s = 0; s < DS; s++) {
                float dA = __expf(dtv * a[s]);
                h[s] = fmaf(dA, h[s], w * sB[t][s]);
                P[s] *= dA;
            }
        }
    }
    long off = ((long)(c * NBB + nbb) * DI + d) * DS;
    float4* he = (float4*)(g_hend + off);
    float4* pe = (float4*)(g_P + off);
#pragma unroll
    for (int s4 = 0; s4 < 4; s4++) {
        he[s4] = make_float4(h[s4 * 4], h[s4 * 4 + 1], h[s4 * 4 + 2], h[s4 * 4 + 3]);
        pe[s4] = make_float4(P[s4 * 4], P[s4 * 4 + 1], P[s4 * 4 + 2], P[s4 * 4 + 3]);
    }
}

// ---------------- scan pass 2: combine carries across chunks ---------------
__global__ void k_carry() {
    int idx = blockIdx.x * blockDim.x + threadIdx.x; // (nbb,d,s)
    if (idx >= NBB * DI * DS) return;
    float h = 0.f;
#pragma unroll
    for (int c = 0; c < CHUNKS; c++) {
        long off = (long)c * (NBB * DI * DS) + idx;
        g_cry[off] = h;
        h = fmaf(g_P[off], h, g_hend[off]);
    }
}

// ---------------- scan pass 3: full scan with carry-in + fused epilogue ----
__global__ __launch_bounds__(256)
void k_scan3(const float* __restrict__ Alog, const float* __restrict__ Dpar, int l) {
    int c   = blockIdx.x;
    int nbb = blockIdx.y;
    int d   = threadIdx.x;
    int nb  = nbb >> 2;
    __shared__ float sB[CLEN][DS];
    __shared__ float sC[CLEN][DS];
    int m0 = nbb * TT + c * CLEN;
    for (int i = d; i < CLEN * 2 * DS; i += 256) {
        int r = i >> 5, j = i & 31;
        float v = g_dbl[(long)(m0 + r) * DBLW + DTR + j];
        if (j < DS) sB[r][j] = v; else sC[r][j - DS] = v;
    }
    float a[DS];
    const float* Ap = Alog + ((long)(nb * NL + l) * DI + d) * DS;
#pragma unroll
    for (int s = 0; s < DS; s++) a[s] = -expf(Ap[s]);
    float A0 = a[0];
    bool ok = true;
#pragma unroll
    for (int s = 0; s < DS; s++)
        ok = ok && (fabsf(a[s] - (float)(s + 1) * A0) <= 1e-4f * fabsf(a[s]) + 1e-7f);
    float Dp = Dpar[(nb * NL + l) * DI + d];
    long off = ((long)(c * NBB + nbb) * DI + d) * DS;
    float h[DS];
#pragma unroll
    for (int s4 = 0; s4 < 4; s4++) {
        float4 cv = *(const float4*)(g_cry + off + s4 * 4);
        h[s4 * 4] = cv.x; h[s4 * 4 + 1] = cv.y; h[s4 * 4 + 2] = cv.z; h[s4 * 4 + 3] = cv.w;
    }
    __syncthreads();
    if (ok) {
        for (int t = 0; t < CLEN; t++) {
            int mr = m0 + t;
            float dtv = g_dt[(long)mr * DI + d];
            float xcv = g_xc[(long)mr * DI + d];
            float w = dtv * xcv;
            float p = __expf(dtv * A0);
            float cum = 1.f, y = 0.f;
#pragma unroll
            for (int s = 0; s < DS; s++) {
                cum *= p;
                h[s] = fmaf(cum, h[s], w * sB[t][s]);
                y = fmaf(h[s], sC[t][s], y);
            }
            float yf = fmaf(Dp, xcv, y);
            float zv = g_xz[(long)mr * (2 * DI) + DI + d];
            g_ym[(long)mr * DI + d] = yf * siluf(zv);
        }
    } else {
        for (int t = 0; t < CLEN; t++) {
            int mr = m0 + t;
            float dtv = g_dt[(long)mr * DI + d];
            float xcv = g_xc[(long)mr * DI + d];
            float w = dtv * xcv;
            float y = 0.f;
#pragma unroll
            for (int s = 0; s < DS; s++) {
                float dA = __expf(dtv * a[s]);
                h[s] = fmaf(dA, h[s], w * sB[t][s]);
                y = fmaf(h[s], sC[t][s], y);
            }
            float yf = fmaf(Dp, xcv, y);
            float zv = g_xz[(long)mr * (2 * DI) + DI + d];
            g_ym[(long)mr * DI + d] = yf * siluf(zv);
        }
    }
}

// ---------------- mean pool over T ----------------------------------------
__global__ void k_pool() {
    int nbb = blockIdx.x;
    int dm  = threadIdx.x;
    float s = 0.f;
    for (int t = 0; t < TT; t++)
        s += g_h[((long)nbb * TT + t) * DM + dm];
    g_pool[nbb * DM + dm] = s * (1.f / (float)TT);
}

// ---------------- final: output proj + Lorentz geometry --------------------
__global__ __launch_bounds__(512)
void k_final(const float* __restrict__ Wop, const float* __restrict__ bop,
             const float* __restrict__ eff, float* __restrict__ out) {
    __shared__ float s_us[NBB][EMB];
    int tid  = threadIdx.x;
    int w    = tid >> 5;
    int lane = tid & 31;
    int nb = w >> 2, b = w & 3;
    int c0 = lane, c1 = lane + 32;
    float es = tanhf(eff[0]);

    // z_t = pooled @ W_op + b_op
    float z0 = bop[nb * EMB + c0];
    float z1 = bop[nb * EMB + c1];
    const float* pl = g_pool + w * DM;
    const float* wp = Wop + (long)nb * DM * EMB;
    for (int k = 0; k < DM; k++) {
        float pv = pl[k];
        z0 = fmaf(pv, wp[k * EMB + c0], z0);
        z1 = fmaf(pv, wp[k * EMB + c1], z1);
    }
    out[nb * (BB * EMB) + b * EMB + c0] = z0;
    out[nb * (BB * EMB) + b * EMB + c1] = z1;

    // z_h = projx(expmap0(z_t * es))
    float v0 = z0 * es, v1 = z1 * es;
    float n2 = warpsum(v0 * v0 + v1 * v1);
    float n  = sqrtf(n2);
    float ncv = fminf(fmaxf(n, EPSV), MAXN);
    float sc  = ncv / fmaxf(n, EPSV);
    v0 *= sc; v1 *= sc;
    float shc = sinhf(ncv) / ncv;
    float sp0 = shc * v0, sp1 = shc * v1;
    float sp2 = warpsum(sp0 * sp0 + sp1 * sp1);
    float tproj = sqrtf(1.f + sp2);
    const int zhb = NBR * BB * EMB; // 1024
    float* oh = out + zhb + nb * (BB * 65) + b * 65;
    if (lane == 0) oh[0] = tproj;
    oh[1 + c0] = sp0;
    oh[1 + c1] = sp1;

    // u = logmap0(z_h)
    float ttv = fmaxf(tproj, 1.f + EPSV);
    float dd  = acoshf(ttv);
    float spn = fmaxf(sqrtf(sp2), EPSV);
    float rr  = dd / spn;
    s_us[w][c0] = rr * sp0;
    s_us[w][c1] = rr * sp1;
    __syncthreads();

    if (w < BB) {
        int b2 = w;
        float u0 = 0.f, u1 = 0.f;
#pragma unroll
        for (int q = 0; q < NBR; q++) {
            u0 += s_us[q * BB + b2][c0];
            u1 += s_us[q * BB + b2][c1];
        }
        const int ctb = zhb + NBR * BB * 65; // 2064
        out[ctb + b2 * EMB + c0] = u0;
        out[ctb + b2 * EMB + c1] = u1;
        float w0 = u0 * es, w1 = u1 * es;
        float m2 = warpsum(w0 * w0 + w1 * w1);
        float mn = sqrtf(m2);
        float mc = fminf(fmaxf(mn, EPSV), MAXN);
        float ms = mc / fmaxf(mn, EPSV);
        w0 *= ms; w1 *= ms;
        float msh = sinhf(mc) / mc;
        float q0 = msh * w0, q1 = msh * w1;
        float q2 = warpsum(q0 * q0 + q1 * q1);
        float t2 = sqrtf(1.f + q2);
        const int chb = ctb + BB * EMB; // 2320
        float* oc = out + chb + b2 * 65;
        if (lane == 0) oc[0] = t2;
        oc[1 + c0] = q0;
        oc[1 + c1] = q1;
    }
}

// ---------------------------------------------------------------------------
extern "C" void kernel_launch(void* const* d_in, const int* in_sizes, int n_in,
                              void* d_out, int out_size) {
    const float* x0   = (const float*)d_in[0];
    const float* x1   = (const float*)d_in[1];
    const float* x2   = (const float*)d_in[2];
    const float* x3   = (const float*)d_in[3];
    const float* Wip  = (const float*)d_in[4];
    const float* bip  = (const float*)d_in[5];
    const float* Win  = (const float*)d_in[6];
    const float* cw   = (const float*)d_in[7];
    const float* cb   = (const float*)d_in[8];
    const float* Wx   = (const float*)d_in[9];
    const float* Wdt  = (const float*)d_in[10];
    const float* bdt  = (const float*)d_in[11];
    const float* Alog = (const float*)d_in[12];
    const float* Dpar = (const float*)d_in[13];
    const float* Wout = (const float*)d_in[14];
    const float* Wop  = (const float*)d_in[15];
    const float* bop  = (const float*)d_in[16];
    const float* eff  = (const float*)d_in[17];
    float* out = (float*)d_out;

    float *p_h, *p_xz, *p_xc, *p_dbl, *p_ym;
    cudaGetSymbolAddress((void**)&p_h,   g_h);
    cudaGetSymbolAddress((void**)&p_xz,  g_xz);
    cudaGetSymbolAddress((void**)&p_xc,  g_xc);
    cudaGetSymbolAddress((void**)&p_dbl, g_dbl);
    cudaGetSymbolAddress((void**)&p_ym,  g_ym);

    k_inproj<<<(ROWS * DM) / 256, 256>>>(x0, x1, x2, x3, Wip, bip);

    for (int l = 0; l < NL; l++) {
        // xz = h @ W_in[:,l]   (M=4096/branch, K=128, N=512)
        k_sgemm<<<dim3(4, RPB / 128, NBR), 256>>>(
            p_h, Win + (long)l * DM * (2 * DI), p_xz,
            RPB, 2 * DI, DM,
            (long)RPB * DM, (long)NL * DM * (2 * DI), (long)RPB * (2 * DI));

        k_conv<<<(ROWS * (DI / 4)) / 256, 256>>>(cw, cb, l);

        // dbl = xc @ W_x[:,l]  (K=256, N=40)
        k_sgemm<<<dim3(1, RPB / 128, NBR), 256>>>(
            p_xc, Wx + (long)l * DI * DBLW, p_dbl,
            RPB, DBLW, DI,
            (long)RPB * DI, (long)NL * DI * DBLW, (long)RPB * DBLW);

        k_dt<<<(ROWS * DI) / 256, 256>>>(Wdt, bdt, l);

        k_scan1<<<dim3(CHUNKS, NBB), 256>>>(Alog, l);
        k_carry<<<(NBB * DI * DS) / 256, 256>>>();
        k_scan3<<<dim3(CHUNKS, NBB), 256>>>(Alog, Dpar, l);

        // h = ym @ W_out[:,l]  (K=256, N=128)
        k_sgemm<<<dim3(1, RPB / 128, NBR), 256>>>(
            p_ym, Wout + (long)l * DI * DM, p_h,
            RPB, DM, DI,
            (long)RPB * DI, (long)NL * DI * DM, (long)RPB * DM);
    }

    k_pool<<<NBB, DM>>>();
    k_final<<<1, 512>>>(Wop, bop, eff, out);
}

// round 5
// speedup vs baseline: 1.9219x; 1.9219x over previous
#include <cuda_runtime.h>
#include <cuda_bf16.h>
#include <math.h>
#include <stdint.h>

#define NBR 4
#define NL  3
#define BB  4
#define TT  1024
#define DIN 32
#define DM  128
#define DI  256
#define DS  16
#define DC  4
#define DTR 8
#define EMB 64
#define ROWS (NBR*BB*TT)   /* 16384 */
#define RPB  (BB*TT)       /* 4096  */
#define NBB  (NBR*BB)      /* 16    */
#define CHUNKS 16
#define CLEN (TT/CHUNKS)   /* 64    */
#define DBLW (DTR+2*DS)    /* 40    */
#define EPSV 1e-7f
#define MAXN 10.0f

// ---------------- scratch (static device memory; no allocs) ----------------
__device__ float          g_h   [ROWS*DM];
__device__ __nv_bfloat16  g_hb  [ROWS*DM];
__device__ float          g_xz  [ROWS*2*DI];
__device__ float          g_xc  [ROWS*DI];
__device__ __nv_bfloat16  g_xcb [ROWS*DI];
__device__ float          g_dbl [ROWS*DBLW];
__device__ float          g_dt  [ROWS*DI];
__device__ __nv_bfloat16  g_ymb [ROWS*DI];
__device__ float g_hend[CHUNKS*NBB*DI*DS];
__device__ float g_P   [CHUNKS*NBB*DI*DS];
__device__ float g_cry [CHUNKS*NBB*DI*DS];
__device__ float g_pool[NBB*DM];
// transposed bf16 weights: [br][l][N][K]
__device__ __nv_bfloat16 g_WinT [NBR*NL*512*128];
__device__ __nv_bfloat16 g_WxT  [NBR*NL*64*256];   // N padded 40->64 (zeros)
__device__ __nv_bfloat16 g_WoutT[NBR*NL*128*256];

__device__ __forceinline__ float warpsum(float v) {
#pragma unroll
    for (int o = 16; o > 0; o >>= 1) v += __shfl_xor_sync(0xffffffffu, v, o);
    return v;
}
__device__ __forceinline__ float siluf(float x) { return x / (1.f + __expf(-x)); }

// ---------------- HMMA 16x8x16 bf16 (baseline PTX, works on compute_103) ---
__device__ __forceinline__ void mma16816(float* d, const uint32_t* a, const uint32_t* b) {
    asm volatile(
        "mma.sync.aligned.m16n8k16.row.col.f32.bf16.bf16.f32 "
        "{%0,%1,%2,%3}, {%4,%5,%6,%7}, {%8,%9}, {%0,%1,%2,%3};"
        : "+f"(d[0]), "+f"(d[1]), "+f"(d[2]), "+f"(d[3])
        : "r"(a[0]), "r"(a[1]), "r"(a[2]), "r"(a[3]), "r"(b[0]), "r"(b[1]));
}

// ---------------- weight transpose + bf16 convert ---------------------------
__global__ void k_prep(const float* __restrict__ Win, const float* __restrict__ Wx,
                       const float* __restrict__ Wout) {
    int gid = blockIdx.x * blockDim.x + threadIdx.x;
    const int N1 = NBR*NL*512*128;
    const int N2 = NBR*NL*64*256;
    const int N3 = NBR*NL*128*256;
    if (gid < N1) {
        int k = gid & 127, n = (gid >> 7) & 511, bl = gid >> 16;
        g_WinT[gid] = __float2bfloat16(Win[(long)bl*128*512 + (long)k*512 + n]);
    } else if (gid < N1 + N2) {
        int t = gid - N1;
        int k = t & 255, n = (t >> 8) & 63, bl = t >> 14;
        g_WxT[t] = __float2bfloat16(n < 40 ? Wx[(long)bl*256*40 + (long)k*40 + n] : 0.f);
    } else if (gid < N1 + N2 + N3) {
        int t = gid - N1 - N2;
        int k = t & 255, n = (t >> 8) & 127, bl = t >> 15;
        g_WoutT[t] = __float2bfloat16(Wout[(long)bl*256*128 + (long)k*128 + n]);
    }
}

// ---------------- HMMA GEMM: C[M,N] = A[M,K] @ Bt[N,K]^T (batched over z) --
// Whole-K panel resident in SMEM; PAD=8 bf16/row -> conflict-free frag loads.
// MODE 0: f32 store   MODE 1: f32 store cols<40   MODE 2: f32 + bf16 store
template<int BM, int BN, int K, int MODE>
__global__ void __launch_bounds__(256, 1)
k_hmma(const __nv_bfloat16* __restrict__ A, const __nv_bfloat16* __restrict__ Bt,
       float* __restrict__ C, __nv_bfloat16* __restrict__ Cb,
       int Nld, long strA, long strB, long strC) {
    constexpr int LDK  = K + 8;
    constexpr int LDKU = LDK / 2;
    constexpr int WARPS_M = BM / 32;
    constexpr int WN = BN / (8 / WARPS_M);
    constexpr int NT = WN / 8;
    constexpr int K8 = K / 8;

    extern __shared__ __align__(16) char smem[];
    __nv_bfloat16* shA = (__nv_bfloat16*)smem;
    __nv_bfloat16* shB = shA + BM * LDK;

    int tid = threadIdx.x;
    int rowBase = blockIdx.y * BM;
    int colBase = blockIdx.x * BN;
    const __nv_bfloat16* Ap = A  + (long)blockIdx.z * strA + (long)rowBase * K;
    const __nv_bfloat16* Bp = Bt + (long)blockIdx.z * strB + (long)colBase * K;
    float* Cp = C + (long)blockIdx.z * strC;
    __nv_bfloat16* Cbp = (MODE == 2) ? (Cb + (long)blockIdx.z * strC) : nullptr;

#pragma unroll 4
    for (int idx = tid; idx < BM * K8; idx += 256) {
        int r = idx / K8, c8 = idx - r * K8;
        *(uint4*)(shA + r * LDK + c8 * 8) = *(const uint4*)(Ap + (long)r * K + c8 * 8);
    }
#pragma unroll 4
    for (int idx = tid; idx < BN * K8; idx += 256) {
        int r = idx / K8, c8 = idx - r * K8;
        *(uint4*)(shB + r * LDK + c8 * 8) = *(const uint4*)(Bp + (long)r * K + c8 * 8);
    }
    __syncthreads();

    int w = tid >> 5, lane = tid & 31;
    int gid = lane >> 2, tig = lane & 3;
    int wm = w % WARPS_M, wn = w / WARPS_M;
    const uint32_t* sAu = (const uint32_t*)shA;
    const uint32_t* sBu = (const uint32_t*)shB;

    float acc[2][NT][4];
#pragma unroll
    for (int mt = 0; mt < 2; mt++)
#pragma unroll
        for (int nt = 0; nt < NT; nt++)
#pragma unroll
            for (int i = 0; i < 4; i++) acc[mt][nt][i] = 0.f;

    int aRow0 = wm * 32 + gid;
    int bRow0 = wn * WN + gid;

#pragma unroll
    for (int kt = 0; kt < K / 16; kt++) {
        int kb2 = kt * 8 + tig;
        uint32_t afr[2][4];
#pragma unroll
        for (int mt = 0; mt < 2; mt++) {
            int r0 = aRow0 + mt * 16;
            afr[mt][0] = sAu[r0 * LDKU + kb2];
            afr[mt][1] = sAu[(r0 + 8) * LDKU + kb2];
            afr[mt][2] = sAu[r0 * LDKU + kb2 + 4];
            afr[mt][3] = sAu[(r0 + 8) * LDKU + kb2 + 4];
        }
        uint32_t bfr[NT][2];
#pragma unroll
        for (int nt = 0; nt < NT; nt++) {
            int rb = bRow0 + nt * 8;
            bfr[nt][0] = sBu[rb * LDKU + kb2];
            bfr[nt][1] = sBu[rb * LDKU + kb2 + 4];
        }
#pragma unroll
        for (int mt = 0; mt < 2; mt++)
#pragma unroll
            for (int nt = 0; nt < NT; nt++)
                mma16816(acc[mt][nt], afr[mt], bfr[nt]);
    }

#pragma unroll
    for (int mt = 0; mt < 2; mt++) {
#pragma unroll
        for (int nt = 0; nt < NT; nt++) {
            int r0 = rowBase + wm * 32 + mt * 16 + gid;
            int c0 = colBase + wn * WN + nt * 8 + 2 * tig;
            if (MODE == 1 && c0 >= 40) continue;
            float2 v0 = make_float2(acc[mt][nt][0], acc[mt][nt][1]);
            float2 v1 = make_float2(acc[mt][nt][2], acc[mt][nt][3]);
            *(float2*)(Cp + (long)r0 * Nld + c0) = v0;
            *(float2*)(Cp + (long)(r0 + 8) * Nld + c0) = v1;
            if (MODE == 2) {
                *(__nv_bfloat162*)(Cbp + (long)r0 * Nld + c0) =
                    __floats2bfloat162_rn(v0.x, v0.y);
                *(__nv_bfloat162*)(Cbp + (long)(r0 + 8) * Nld + c0) =
                    __floats2bfloat162_rn(v1.x, v1.y);
            }
        }
    }
}

// ---------------- input projection: hb = bf16(x @ W_ip + b_ip) -------------
__global__ void k_inproj(const float* __restrict__ x0, const float* __restrict__ x1,
                         const float* __restrict__ x2, const float* __restrict__ x3,
                         const float* __restrict__ Wip, const float* __restrict__ bip) {
    int gid = blockIdx.x * blockDim.x + threadIdx.x;
    if (gid >= ROWS * DM) return;
    int dm = gid & (DM - 1);
    int m  = gid / DM;
    int nb = m / RPB;
    int r  = m - nb * RPB;
    const float* x = (nb == 0) ? x0 : (nb == 1) ? x1 : (nb == 2) ? x2 : x3;
    const float* xr = x + r * DIN;
    const float* w  = Wip + nb * DIN * DM + dm;
    float acc = bip[nb * DM + dm];
#pragma unroll
    for (int k = 0; k < DIN; k++) acc = fmaf(xr[k], w[k * DM], acc);
    g_hb[gid] = __float2bfloat16(acc);
}

// ---------------- causal depthwise conv (D_CONV=4) + SiLU ------------------
__global__ void k_conv(const float* __restrict__ cw, const float* __restrict__ cb, int l) {
    int gid = blockIdx.x * blockDim.x + threadIdx.x;
    if (gid >= ROWS * (DI / 4)) return;
    int q  = gid & 63;
    int m  = gid >> 6;
    int d0 = q * 4;
    int nb = m / RPB;
    int t  = m & (TT - 1);
    const float* cwp = cw + (((long)(nb * NL + l)) * DI + d0) * DC;
    float cwa[16];
    *(float4*)(cwa + 0)  = *(const float4*)(cwp + 0);
    *(float4*)(cwa + 4)  = *(const float4*)(cwp + 4);
    *(float4*)(cwa + 8)  = *(const float4*)(cwp + 8);
    *(float4*)(cwa + 12) = *(const float4*)(cwp + 12);
    const float* cbp = cb + (long)(nb * NL + l) * DI + d0;
    float a0 = cbp[0], a1 = cbp[1], a2 = cbp[2], a3 = cbp[3];
#pragma unroll
    for (int k = 0; k < DC; k++) {
        int tk = t + k - (DC - 1);
        if (tk >= 0) {
            const float* xp = g_xz + (long)(m + k - (DC - 1)) * (2 * DI) + d0;
            float4 xv = *(const float4*)xp;
            a0 = fmaf(xv.x, cwa[0 * DC + k], a0);
            a1 = fmaf(xv.y, cwa[1 * DC + k], a1);
            a2 = fmaf(xv.z, cwa[2 * DC + k], a2);
            a3 = fmaf(xv.w, cwa[3 * DC + k], a3);
        }
    }
    float4 o;
    o.x = siluf(a0); o.y = siluf(a1); o.z = siluf(a2); o.w = siluf(a3);
    *(float4*)(g_xc + (long)m * DI + d0) = o;
    __nv_bfloat162* xb = (__nv_bfloat162*)(g_xcb + (long)m * DI + d0);
    xb[0] = __floats2bfloat162_rn(o.x, o.y);
    xb[1] = __floats2bfloat162_rn(o.z, o.w);
}

// ---------------- dt = softplus(dbl[:, :8] @ W_dt + b_dt) ------------------
__global__ void k_dt(const float* __restrict__ Wdt, const float* __restrict__ bdt, int l) {
    int gid = blockIdx.x * blockDim.x + threadIdx.x;
    if (gid >= ROWS * DI) return;
    int d = gid & (DI - 1);
    int m = gid >> 8;
    int nb = m / RPB;
    const float* db = g_dbl + (long)m * DBLW;
    const float* w  = Wdt + (long)(nb * NL + l) * DTR * DI + d;
    float u = bdt[(nb * NL + l) * DI + d];
#pragma unroll
    for (int r = 0; r < DTR; r++) u = fmaf(db[r], w[r * DI], u);
    float sp = (u > 20.f) ? u : log1pf(__expf(u));
    g_dt[gid] = sp;
}

// ---------------- scan pass 1: per-chunk local scan + dA product -----------
__global__ void __launch_bounds__(256)
k_scan1(const float* __restrict__ Alog, int l) {
    int c = blockIdx.x, nbb = blockIdx.y, d = threadIdx.x, nb = nbb >> 2;
    __shared__ float sB[CLEN][DS];
    int m0 = nbb * TT + c * CLEN;
    for (int i = d; i < CLEN * DS; i += 256) {
        int r = i >> 4, j = i & 15;
        sB[r][j] = g_dbl[(long)(m0 + r) * DBLW + DTR + j];
    }
    float a[DS];
    const float* Ap = Alog + ((long)(nb * NL + l) * DI + d) * DS;
#pragma unroll
    for (int s = 0; s < DS; s++) a[s] = -expf(Ap[s]);
    float A0 = a[0];
    bool ok = true;
#pragma unroll
    for (int s = 0; s < DS; s++)
        ok = ok && (fabsf(a[s] - (float)(s + 1) * A0) <= 1e-4f * fabsf(a[s]) + 1e-7f);
    __syncthreads();
    float h[DS], P[DS];
#pragma unroll
    for (int s = 0; s < DS; s++) { h[s] = 0.f; P[s] = 1.f; }
    if (ok) {
        for (int t = 0; t < CLEN; t++) {
            int mr = m0 + t;
            float dtv = g_dt[(long)mr * DI + d];
            float xcv = g_xc[(long)mr * DI + d];
            float w = dtv * xcv;
            float p = __expf(dtv * A0);
            float cum = 1.f;
#pragma unroll
            for (int s = 0; s < DS; s++) {
                cum *= p;
                h[s] = fmaf(cum, h[s], w * sB[t][s]);
                P[s] *= cum;
            }
        }
    } else {
        for (int t = 0; t < CLEN; t++) {
            int mr = m0 + t;
            float dtv = g_dt[(long)mr * DI + d];
            float xcv = g_xc[(long)mr * DI + d];
            float w = dtv * xcv;
#pragma unroll
            for (int s = 0; s < DS; s++) {
                float dA = __expf(dtv * a[s]);
                h[s] = fmaf(dA, h[s], w * sB[t][s]);
                P[s] *= dA;
            }
        }
    }
    long off = ((long)(c * NBB + nbb) * DI + d) * DS;
    float4* he = (float4*)(g_hend + off);
    float4* pe = (float4*)(g_P + off);
#pragma unroll
    for (int s4 = 0; s4 < 4; s4++) {
        he[s4] = make_float4(h[s4*4], h[s4*4+1], h[s4*4+2], h[s4*4+3]);
        pe[s4] = make_float4(P[s4*4], P[s4*4+1], P[s4*4+2], P[s4*4+3]);
    }
}

// ---------------- scan pass 2: combine carries across chunks ---------------
__global__ void k_carry() {
    int idx = blockIdx.x * blockDim.x + threadIdx.x;
    if (idx >= NBB * DI * DS) return;
    float h = 0.f;
#pragma unroll
    for (int c = 0; c < CHUNKS; c++) {
        long off = (long)c * (NBB * DI * DS) + idx;
        g_cry[off] = h;
        h = fmaf(g_P[off], h, g_hend[off]);
    }
}

// ---------------- scan pass 3: full scan + fused epilogue (bf16 ym) --------
__global__ void __launch_bounds__(256)
k_scan3(const float* __restrict__ Alog, const float* __restrict__ Dpar, int l) {
    int c = blockIdx.x, nbb = blockIdx.y, d = threadIdx.x, nb = nbb >> 2;
    __shared__ float sB[CLEN][DS];
    __shared__ float sC[CLEN][DS];
    int m0 = nbb * TT + c * CLEN;
    for (int i = d; i < CLEN * 2 * DS; i += 256) {
        int r = i >> 5, j = i & 31;
        float v = g_dbl[(long)(m0 + r) * DBLW + DTR + j];
        if (j < DS) sB[r][j] = v; else sC[r][j - DS] = v;
    }
    float a[DS];
    const float* Ap = Alog + ((long)(nb * NL + l) * DI + d) * DS;
#pragma unroll
    for (int s = 0; s < DS; s++) a[s] = -expf(Ap[s]);
    float A0 = a[0];
    bool ok = true;
#pragma unroll
    for (int s = 0; s < DS; s++)
        ok = ok && (fabsf(a[s] - (float)(s + 1) * A0) <= 1e-4f * fabsf(a[s]) + 1e-7f);
    float Dp = Dpar[(nb * NL + l) * DI + d];
    long off = ((long)(c * NBB + nbb) * DI + d) * DS;
    float h[DS];
#pragma unroll
    for (int s4 = 0; s4 < 4; s4++) {
        float4 cv = *(const float4*)(g_cry + off + s4 * 4);
        h[s4*4] = cv.x; h[s4*4+1] = cv.y; h[s4*4+2] = cv.z; h[s4*4+3] = cv.w;
    }
    __syncthreads();
    if (ok) {
        for (int t = 0; t < CLEN; t++) {
            int mr = m0 + t;
            float dtv = g_dt[(long)mr * DI + d];
            float xcv = g_xc[(long)mr * DI + d];
            float w = dtv * xcv;
            float p = __expf(dtv * A0);
            float cum = 1.f, y = 0.f;
#pragma unroll
            for (int s = 0; s < DS; s++) {
                cum *= p;
                h[s] = fmaf(cum, h[s], w * sB[t][s]);
                y = fmaf(h[s], sC[t][s], y);
            }
            float yf = fmaf(Dp, xcv, y);
            float zv = g_xz[(long)mr * (2 * DI) + DI + d];
            g_ymb[(long)mr * DI + d] = __float2bfloat16(yf * siluf(zv));
        }
    } else {
        for (int t = 0; t < CLEN; t++) {
            int mr = m0 + t;
            float dtv = g_dt[(long)mr * DI + d];
            float xcv = g_xc[(long)mr * DI + d];
            float w = dtv * xcv;
            float y = 0.f;
#pragma unroll
            for (int s = 0; s < DS; s++) {
                float dA = __expf(dtv * a[s]);
                h[s] = fmaf(dA, h[s], w * sB[t][s]);
                y = fmaf(h[s], sC[t][s], y);
            }
            float yf = fmaf(Dp, xcv, y);
            float zv = g_xz[(long)mr * (2 * DI) + DI + d];
            g_ymb[(long)mr * DI + d] = __float2bfloat16(yf * siluf(zv));
        }
    }
}

// ---------------- mean pool over T ----------------------------------------
__global__ void k_pool() {
    int nbb = blockIdx.x;
    int dm  = threadIdx.x;
    float s0 = 0.f, s1 = 0.f, s2 = 0.f, s3 = 0.f;
    for (int t = 0; t < TT; t += 4) {
        s0 += g_h[((long)nbb * TT + t + 0) * DM + dm];
        s1 += g_h[((long)nbb * TT + t + 1) * DM + dm];
        s2 += g_h[((long)nbb * TT + t + 2) * DM + dm];
        s3 += g_h[((long)nbb * TT + t + 3) * DM + dm];
    }
    g_pool[nbb * DM + dm] = ((s0 + s1) + (s2 + s3)) * (1.f / (float)TT);
}

// ---------------- final: output proj + Lorentz geometry --------------------
__global__ void __launch_bounds__(512)
k_final(const float* __restrict__ Wop, const float* __restrict__ bop,
        const float* __restrict__ eff, float* __restrict__ out) {
    __shared__ float s_us[NBB][EMB];
    int tid = threadIdx.x, w = tid >> 5, lane = tid & 31;
    int nb = w >> 2, b = w & 3;
    int c0 = lane, c1 = lane + 32;
    float es = tanhf(eff[0]);

    float z0 = bop[nb * EMB + c0];
    float z1 = bop[nb * EMB + c1];
    const float* pl = g_pool + w * DM;
    const float* wp = Wop + (long)nb * DM * EMB;
    for (int k = 0; k < DM; k++) {
        float pv = pl[k];
        z0 = fmaf(pv, wp[k * EMB + c0], z0);
        z1 = fmaf(pv, wp[k * EMB + c1], z1);
    }
    out[nb * (BB * EMB) + b * EMB + c0] = z0;
    out[nb * (BB * EMB) + b * EMB + c1] = z1;

    float v0 = z0 * es, v1 = z1 * es;
    float n2 = warpsum(v0 * v0 + v1 * v1);
    float n  = sqrtf(n2);
    float ncv = fminf(fmaxf(n, EPSV), MAXN);
    float sc  = ncv / fmaxf(n, EPSV);
    v0 *= sc; v1 *= sc;
    float shc = sinhf(ncv) / ncv;
    float sp0 = shc * v0, sp1 = shc * v1;
    float sp2 = warpsum(sp0 * sp0 + sp1 * sp1);
    float tproj = sqrtf(1.f + sp2);
    const int zhb = NBR * BB * EMB;
    float* oh = out + zhb + nb * (BB * 65) + b * 65;
    if (lane == 0) oh[0] = tproj;
    oh[1 + c0] = sp0;
    oh[1 + c1] = sp1;

    float ttv = fmaxf(tproj, 1.f + EPSV);
    float dd  = acoshf(ttv);
    float spn = fmaxf(sqrtf(sp2), EPSV);
    float rr  = dd / spn;
    s_us[w][c0] = rr * sp0;
    s_us[w][c1] = rr * sp1;
    __syncthreads();

    if (w < BB) {
        int b2 = w;
        float u0 = 0.f, u1 = 0.f;
#pragma unroll
        for (int q = 0; q < NBR; q++) {
            u0 += s_us[q * BB + b2][c0];
            u1 += s_us[q * BB + b2][c1];
        }
        const int ctb = zhb + NBR * BB * 65;
        out[ctb + b2 * EMB + c0] = u0;
        out[ctb + b2 * EMB + c1] = u1;
        float w0 = u0 * es, w1 = u1 * es;
        float m2 = warpsum(w0 * w0 + w1 * w1);
        float mn = sqrtf(m2);
        float mc = fminf(fmaxf(mn, EPSV), MAXN);
        float ms = mc / fmaxf(mn, EPSV);
        w0 *= ms; w1 *= ms;
        float msh = sinhf(mc) / mc;
        float q0 = msh * w0, q1 = msh * w1;
        float q2 = warpsum(q0 * q0 + q1 * q1);
        float t2 = sqrtf(1.f + q2);
        const int chb = ctb + BB * EMB;
        float* oc = out + chb + b2 * 65;
        if (lane == 0) oc[0] = t2;
        oc[1 + c0] = q0;
        oc[1 + c1] = q1;
    }
}

// ---------------------------------------------------------------------------
extern "C" void kernel_launch(void* const* d_in, const int* in_sizes, int n_in,
                              void* d_out, int out_size) {
    const float* x0   = (const float*)d_in[0];
    const float* x1   = (const float*)d_in[1];
    const float* x2   = (const float*)d_in[2];
    const float* x3   = (const float*)d_in[3];
    const float* Wip  = (const float*)d_in[4];
    const float* bip  = (const float*)d_in[5];
    const float* Win  = (const float*)d_in[6];
    const float* cw   = (const float*)d_in[7];
    const float* cb   = (const float*)d_in[8];
    const float* Wx   = (const float*)d_in[9];
    const float* Wdt  = (const float*)d_in[10];
    const float* bdt  = (const float*)d_in[11];
    const float* Alog = (const float*)d_in[12];
    const float* Dpar = (const float*)d_in[13];
    const float* Wout = (const float*)d_in[14];
    const float* Wop  = (const float*)d_in[15];
    const float* bop  = (const float*)d_in[16];
    const float* eff  = (const float*)d_in[17];
    float* out = (float*)d_out;

    __nv_bfloat16 *p_hb, *p_xcb, *p_ymb, *p_WinT, *p_WxT, *p_WoutT;
    float *p_xz, *p_dbl, *p_h;
    cudaGetSymbolAddress((void**)&p_hb,    g_hb);
    cudaGetSymbolAddress((void**)&p_xcb,   g_xcb);
    cudaGetSymbolAddress((void**)&p_ymb,   g_ymb);
    cudaGetSymbolAddress((void**)&p_WinT,  g_WinT);
    cudaGetSymbolAddress((void**)&p_WxT,   g_WxT);
    cudaGetSymbolAddress((void**)&p_WoutT, g_WoutT);
    cudaGetSymbolAddress((void**)&p_xz,    g_xz);
    cudaGetSymbolAddress((void**)&p_dbl,   g_dbl);
    cudaGetSymbolAddress((void**)&p_h,     g_h);

    const int SM_G1 = (128 + 128) * (128 + 8) * 2; // 69632
    const int SM_G2 = (64 + 64)   * (256 + 8) * 2; // 67584
    const int SM_G3 = (64 + 128)  * (256 + 8) * 2; // 101376
    cudaFuncSetAttribute(k_hmma<128,128,128,0>, cudaFuncAttributeMaxDynamicSharedMemorySize, SM_G1);
    cudaFuncSetAttribute(k_hmma<64,64,256,1>,   cudaFuncAttributeMaxDynamicSharedMemorySize, SM_G2);
    cudaFuncSetAttribute(k_hmma<64,128,256,2>,  cudaFuncAttributeMaxDynamicSharedMemorySize, SM_G3);

    k_prep<<<(NBR*NL*512*128 + NBR*NL*64*256 + NBR*NL*128*256 + 255) / 256, 256>>>(Win, Wx, Wout);
    k_inproj<<<(ROWS * DM) / 256, 256>>>(x0, x1, x2, x3, Wip, bip);

    for (int l = 0; l < NL; l++) {
        // xz = h @ W_in[:,l]   (M=4096, N=512, K=128) per branch
        k_hmma<128,128,128,0><<<dim3(4, RPB/128, NBR), 256, SM_G1>>>(
            p_hb, p_WinT + (long)l*512*128, p_xz, nullptr,
            512, (long)RPB*128, (long)NL*512*128, (long)RPB*512);

        k_conv<<<(ROWS * (DI/4)) / 256, 256>>>(cw, cb, l);

        // dbl = xc @ W_x[:,l]  (N=40 padded 64, K=256)
        k_hmma<64,64,256,1><<<dim3(1, RPB/64, NBR), 256, SM_G2>>>(
            p_xcb, p_WxT + (long)l*64*256, p_dbl, nullptr,
            DBLW, (long)RPB*256, (long)NL*64*256, (long)RPB*DBLW);

        k_dt<<<(ROWS * DI) / 256, 256>>>(Wdt, bdt, l);

        k_scan1<<<dim3(CHUNKS, NBB), 256>>>(Alog, l);
        k_carry<<<(NBB * DI * DS) / 256, 256>>>();
        k_scan3<<<dim3(CHUNKS, NBB), 256>>>(Alog, Dpar, l);

        // h = ym @ W_out[:,l]  (N=128, K=256), f32 + bf16 outputs
        k_hmma<64,128,256,2><<<dim3(1, RPB/64, NBR), 256, SM_G3>>>(
            p_ymb, p_WoutT + (long)l*128*256, p_h, p_hb,
            DM, (long)RPB*256, (long)NL*128*256, (long)RPB*DM);
    }

    k_pool<<<NBB, DM>>>();
    k_final<<<1, 512>>>(Wop, bop, eff, out);
}

// round 7
// speedup vs baseline: 2.2005x; 1.1450x over previous
#include <cuda_runtime.h>
#include <cuda_bf16.h>
#include <math.h>
#include <stdint.h>

#define NBR 4
#define NL  3
#define BB  4
#define TT  1024
#define DIN 32
#define DM  128
#define DI  256
#define DS  16
#define DC  4
#define DTR 8
#define EMB 64
#define ROWS (NBR*BB*TT)   /* 16384 */
#define RPB  (BB*TT)       /* 4096  */
#define NBB  (NBR*BB)      /* 16    */
#define CHUNKS 32
#define CLEN (TT/CHUNKS)   /* 32    */
#define DBLW (DTR+2*DS)    /* 40    */
#define EPSV 1e-7f
#define MAXN 10.0f

// ---------------- scratch (static device memory; no allocs) ----------------
__device__ float          g_h    [ROWS*DM];
__device__ __nv_bfloat16  g_hb   [ROWS*DM];
__device__ float          g_xz   [ROWS*2*DI];
__device__ float          g_xc   [ROWS*DI];
__device__ __nv_bfloat16  g_xcb  [ROWS*DI];
__device__ float          g_dbl  [ROWS*DBLW];
__device__ float          g_dt   [ROWS*DI];
__device__ __nv_bfloat16  g_ymb  [ROWS*DI];
__device__ float g_hend [CHUNKS*NBB*DI*DS];
__device__ float g_P    [CHUNKS*NBB*DI*DS];
__device__ float g_cry  [CHUNKS*NBB*DI*DS];
__device__ float g_poolp[NBB*8*DM];
__device__ float g_pool [NBB*DM];
// transposed bf16 weights: [br][l][N][K]
__device__ __nv_bfloat16 g_WinT [NBR*NL*512*128];
__device__ __nv_bfloat16 g_WxT  [NBR*NL*64*256];   // N padded 40->64 (zeros)
__device__ __nv_bfloat16 g_WoutT[NBR*NL*128*256];

__device__ __forceinline__ float warpsum(float v) {
#pragma unroll
    for (int o = 16; o > 0; o >>= 1) v += __shfl_xor_sync(0xffffffffu, v, o);
    return v;
}
__device__ __forceinline__ float siluf(float x) { return x / (1.f + __expf(-x)); }

// ---------------- HMMA 16x8x16 bf16 (baseline PTX, works on compute_103) ---
__device__ __forceinline__ void mma16816(float* d, const uint32_t* a, const uint32_t* b) {
    asm volatile(
        "mma.sync.aligned.m16n8k16.row.col.f32.bf16.bf16.f32 "
        "{%0,%1,%2,%3}, {%4,%5,%6,%7}, {%8,%9}, {%0,%1,%2,%3};"
        : "+f"(d[0]), "+f"(d[1]), "+f"(d[2]), "+f"(d[3])
        : "r"(a[0]), "r"(a[1]), "r"(a[2]), "r"(a[3]), "r"(b[0]), "r"(b[1]));
}

// ---------------- coalesced transpose + bf16 convert: [K,N] -> [NPAD,K] ----
template<int KD, int ND, int NPAD>
__global__ void k_tr(const float* __restrict__ W, __nv_bfloat16* __restrict__ out) {
    __shared__ float tile[32][33];
    int mIdx = blockIdx.z;
    const float* Wm = W + (long)mIdx * KD * ND;
    __nv_bfloat16* om = out + (long)mIdx * NPAD * KD;
    int n0 = blockIdx.x * 32, k0 = blockIdx.y * 32;
    int tx = threadIdx.x, ty = threadIdx.y;   // 32 x 8
#pragma unroll
    for (int i = 0; i < 32; i += 8) {
        int k = k0 + ty + i, n = n0 + tx;
        tile[ty + i][tx] = (n < ND) ? Wm[(long)k * ND + n] : 0.f;
    }
    __syncthreads();
#pragma unroll
    for (int i = 0; i < 32; i += 8) {
        int n = n0 + ty + i, k = k0 + tx;
        if (n < NPAD) om[(long)n * KD + k] = __float2bfloat16(tile[tx][ty + i]);
    }
}

// ---------------- HMMA GEMM: C[M,N] = A[M,K] @ Bt[N,K]^T (batched over z) --
// MODE 0: f32 store   MODE 1: f32 store cols<40   MODE 2: f32 + bf16 store
template<int BM, int BN, int K, int MODE>
__global__ void __launch_bounds__(256, 1)
k_hmma(const __nv_bfloat16* __restrict__ A, const __nv_bfloat16* __restrict__ Bt,
       float* __restrict__ C, __nv_bfloat16* __restrict__ Cb,
       int Nld, long strA, long strB, long strC) {
    constexpr int LDK  = K + 8;
    constexpr int LDKU = LDK / 2;
    constexpr int WARPS_M = BM / 32;
    constexpr int WN = BN / (8 / WARPS_M);
    constexpr int NT = WN / 8;
    constexpr int K8 = K / 8;

    extern __shared__ __align__(16) char smem[];
    __nv_bfloat16* shA = (__nv_bfloat16*)smem;
    __nv_bfloat16* shB = shA + BM * LDK;

    int tid = threadIdx.x;
    int rowBase = blockIdx.y * BM;
    int colBase = blockIdx.x * BN;
    const __nv_bfloat16* Ap = A  + (long)blockIdx.z * strA + (long)rowBase * K;
    const __nv_bfloat16* Bp = Bt + (long)blockIdx.z * strB + (long)colBase * K;
    float* Cp = C + (long)blockIdx.z * strC;
    __nv_bfloat16* Cbp = (MODE == 2) ? (Cb + (long)blockIdx.z * strC) : nullptr;

#pragma unroll 4
    for (int idx = tid; idx < BM * K8; idx += 256) {
        int r = idx / K8, c8 = idx - r * K8;
        *(uint4*)(shA + r * LDK + c8 * 8) = *(const uint4*)(Ap + (long)r * K + c8 * 8);
    }
#pragma unroll 4
    for (int idx = tid; idx < BN * K8; idx += 256) {
        int r = idx / K8, c8 = idx - r * K8;
        *(uint4*)(shB + r * LDK + c8 * 8) = *(const uint4*)(Bp + (long)r * K + c8 * 8);
    }
    __syncthreads();

    int w = tid >> 5, lane = tid & 31;
    int gid = lane >> 2, tig = lane & 3;
    int wm = w % WARPS_M, wn = w / WARPS_M;
    const uint32_t* sAu = (const uint32_t*)shA;
    const uint32_t* sBu = (const uint32_t*)shB;

    float acc[2][NT][4];
#pragma unroll
    for (int mt = 0; mt < 2; mt++)
#pragma unroll
        for (int nt = 0; nt < NT; nt++)
#pragma unroll
            for (int i = 0; i < 4; i++) acc[mt][nt][i] = 0.f;

    int aRow0 = wm * 32 + gid;
    int bRow0 = wn * WN + gid;

#pragma unroll
    for (int kt = 0; kt < K / 16; kt++) {
        int kb2 = kt * 8 + tig;
        uint32_t afr[2][4];
#pragma unroll
        for (int mt = 0; mt < 2; mt++) {
            int r0 = aRow0 + mt * 16;
            afr[mt][0] = sAu[r0 * LDKU + kb2];
            afr[mt][1] = sAu[(r0 + 8) * LDKU + kb2];
            afr[mt][2] = sAu[r0 * LDKU + kb2 + 4];
            afr[mt][3] = sAu[(r0 + 8) * LDKU + kb2 + 4];
        }
        uint32_t bfr[NT][2];
#pragma unroll
        for (int nt = 0; nt < NT; nt++) {
            int rb = bRow0 + nt * 8;
            bfr[nt][0] = sBu[rb * LDKU + kb2];
            bfr[nt][1] = sBu[rb * LDKU + kb2 + 4];
        }
#pragma unroll
        for (int mt = 0; mt < 2; mt++)
#pragma unroll
            for (int nt = 0; nt < NT; nt++)
                mma16816(acc[mt][nt], afr[mt], bfr[nt]);
    }

#pragma unroll
    for (int mt = 0; mt < 2; mt++) {
#pragma unroll
        for (int nt = 0; nt < NT; nt++) {
            int r0 = rowBase + wm * 32 + mt * 16 + gid;
            int c0 = colBase + wn * WN + nt * 8 + 2 * tig;
            if (MODE == 1 && c0 >= 40) continue;
            float2 v0 = make_float2(acc[mt][nt][0], acc[mt][nt][1]);
            float2 v1 = make_float2(acc[mt][nt][2], acc[mt][nt][3]);
            *(float2*)(Cp + (long)r0 * Nld + c0) = v0;
            *(float2*)(Cp + (long)(r0 + 8) * Nld + c0) = v1;
            if (MODE == 2) {
                *(__nv_bfloat162*)(Cbp + (long)r0 * Nld + c0) =
                    __floats2bfloat162_rn(v0.x, v0.y);
                *(__nv_bfloat162*)(Cbp + (long)(r0 + 8) * Nld + c0) =
                    __floats2bfloat162_rn(v1.x, v1.y);
            }
        }
    }
}

// ---------------- input projection: hb = bf16(x @ W_ip + b_ip) -------------
__global__ void k_inproj(const float* __restrict__ x0, const float* __restrict__ x1,
                         const float* __restrict__ x2, const float* __restrict__ x3,
                         const float* __restrict__ Wip, const float* __restrict__ bip) {
    int gid = blockIdx.x * blockDim.x + threadIdx.x;
    if (gid >= ROWS * DM) return;
    int dm = gid & (DM - 1);
    int m  = gid / DM;
    int nb = m / RPB;
    int r  = m - nb * RPB;
    const float* x = (nb == 0) ? x0 : (nb == 1) ? x1 : (nb == 2) ? x2 : x3;
    const float* xr = x + r * DIN;
    const float* w  = Wip + nb * DIN * DM + dm;
    float acc = bip[nb * DM + dm];
#pragma unroll
    for (int k = 0; k < DIN; k++) acc = fmaf(xr[k], w[k * DM], acc);
    g_hb[gid] = __float2bfloat16(acc);
}

// ---------------- causal depthwise conv + SiLU (4 timesteps / thread) ------
__global__ void __launch_bounds__(256)
k_conv(const float* __restrict__ cw, const float* __restrict__ cb, int l) {
    int gid = blockIdx.x * blockDim.x + threadIdx.x;
    if (gid >= (ROWS / 4) * 64) return;
    int q  = gid & 63;            // channel group (4 channels)
    int m4 = gid >> 6;            // group of 4 rows
    int d0 = q * 4;
    int nb = m4 / (RPB / 4);
    int t0 = (m4 & (TT / 4 - 1)) * 4;
    int mrow = m4 * 4;

    const float* cwp = cw + (((long)(nb * NL + l)) * DI + d0) * DC;
    float cwa[16];
    *(float4*)(cwa + 0)  = *(const float4*)(cwp + 0);
    *(float4*)(cwa + 4)  = *(const float4*)(cwp + 4);
    *(float4*)(cwa + 8)  = *(const float4*)(cwp + 8);
    *(float4*)(cwa + 12) = *(const float4*)(cwp + 12);
    const float* cbp = cb + (long)(nb * NL + l) * DI + d0;
    float4 bias = *(const float4*)cbp;

    float4 xr[7];
#pragma unroll
    for (int j = 0; j < 7; j++) {
        int tr = t0 + j - 3;
        if (tr >= 0)
            xr[j] = *(const float4*)(g_xz + (long)(mrow + j - 3) * (2 * DI) + d0);
        else
            xr[j] = make_float4(0.f, 0.f, 0.f, 0.f);
    }
#pragma unroll
    for (int i = 0; i < 4; i++) {
        float a0 = bias.x, a1 = bias.y, a2 = bias.z, a3 = bias.w;
#pragma unroll
        for (int k = 0; k < DC; k++) {
            float4 xv = xr[i + k];
            a0 = fmaf(xv.x, cwa[0 * DC + k], a0);
            a1 = fmaf(xv.y, cwa[1 * DC + k], a1);
            a2 = fmaf(xv.z, cwa[2 * DC + k], a2);
            a3 = fmaf(xv.w, cwa[3 * DC + k], a3);
        }
        float4 o;
        o.x = siluf(a0); o.y = siluf(a1); o.z = siluf(a2); o.w = siluf(a3);
        long row = mrow + i;
        *(float4*)(g_xc + row * DI + d0) = o;
        __nv_bfloat162* xb = (__nv_bfloat162*)(g_xcb + row * DI + d0);
        xb[0] = __floats2bfloat162_rn(o.x, o.y);
        xb[1] = __floats2bfloat162_rn(o.z, o.w);
    }
}

// ---------------- scan pass 1: fused dt + per-chunk local scan -------------
__global__ void __launch_bounds__(256)
k_scan1(const float* __restrict__ Alog, const float* __restrict__ Wdt,
        const float* __restrict__ bdt, int l) {
    int c = blockIdx.x, nbb = blockIdx.y, d = threadIdx.x, nb = nbb >> 2;
    __shared__ float sD[CLEN][DTR];
    __shared__ float sB[CLEN][DS];
    int m0 = nbb * TT + c * CLEN;
    for (int i = d; i < CLEN * (DTR + DS); i += 256) {
        int r = i / (DTR + DS), j = i - r * (DTR + DS);
        float v = g_dbl[(long)(m0 + r) * DBLW + j];
        if (j < DTR) sD[r][j] = v; else sB[r][j - DTR] = v;
    }
    float a[DS];
    const float* Ap = Alog + ((long)(nb * NL + l) * DI + d) * DS;
#pragma unroll
    for (int s = 0; s < DS; s++) a[s] = -expf(Ap[s]);
    float A0 = a[0];
    bool ok = true;
#pragma unroll
    for (int s = 0; s < DS; s++)
        ok = ok && (fabsf(a[s] - (float)(s + 1) * A0) <= 1e-4f * fabsf(a[s]) + 1e-7f);
    float wdt[DTR];
    const float* wdp = Wdt + (long)(nb * NL + l) * DTR * DI + d;
#pragma unroll
    for (int r = 0; r < DTR; r++) wdt[r] = wdp[r * DI];
    float bdtv = bdt[(nb * NL + l) * DI + d];
    __syncthreads();

    float h[DS], P[DS];
#pragma unroll
    for (int s = 0; s < DS; s++) { h[s] = 0.f; P[s] = 1.f; }
    if (ok) {
        for (int t = 0; t < CLEN; t++) {
            int mr = m0 + t;
            float u = bdtv;
#pragma unroll
            for (int r = 0; r < DTR; r++) u = fmaf(sD[t][r], wdt[r], u);
            float dtv = (u > 20.f) ? u : __logf(1.f + __expf(u));
            g_dt[(long)mr * DI + d] = dtv;
            float xcv = g_xc[(long)mr * DI + d];
            float w = dtv * xcv;
            float p = __expf(dtv * A0);
            float cum = 1.f;
#pragma unroll
            for (int s = 0; s < DS; s++) {
                cum *= p;
                h[s] = fmaf(cum, h[s], w * sB[t][s]);
                P[s] *= cum;
            }
        }
    } else {
        for (int t = 0; t < CLEN; t++) {
            int mr = m0 + t;
            float u = bdtv;
#pragma unroll
            for (int r = 0; r < DTR; r++) u = fmaf(sD[t][r], wdt[r], u);
            float dtv = (u > 20.f) ? u : __logf(1.f + __expf(u));
            g_dt[(long)mr * DI + d] = dtv;
            float xcv = g_xc[(long)mr * DI + d];
            float w = dtv * xcv;
#pragma unroll
            for (int s = 0; s < DS; s++) {
                float dA = __expf(dtv * a[s]);
                h[s] = fmaf(dA, h[s], w * sB[t][s]);
                P[s] *= dA;
            }
        }
    }
    long off = ((long)(c * NBB + nbb) * DI + d) * DS;
    float4* he = (float4*)(g_hend + off);
    float4* pe = (float4*)(g_P + off);
#pragma unroll
    for (int s4 = 0; s4 < 4; s4++) {
        he[s4] = make_float4(h[s4*4], h[s4*4+1], h[s4*4+2], h[s4*4+3]);
        pe[s4] = make_float4(P[s4*4], P[s4*4+1], P[s4*4+2], P[s4*4+3]);
    }
}

// ---------------- scan pass 2: combine carries across chunks ---------------
__global__ void k_carry() {
    int idx = blockIdx.x * blockDim.x + threadIdx.x;
    if (idx >= NBB * DI * DS) return;
    float h = 0.f;
#pragma unroll
    for (int c = 0; c < CHUNKS; c++) {
        long off = (long)c * (NBB * DI * DS) + idx;
        g_cry[off] = h;
        h = fmaf(g_P[off], h, g_hend[off]);
    }
}

// ---------------- scan pass 3: full scan + fused epilogue (bf16 ym) --------
__global__ void __launch_bounds__(256)
k_scan3(const float* __restrict__ Alog, const float* __restrict__ Dpar, int l) {
    int c = blockIdx.x, nbb = blockIdx.y, d = threadIdx.x, nb = nbb >> 2;
    __shared__ float sB[CLEN][DS];
    __shared__ float sC[CLEN][DS];
    int m0 = nbb * TT + c * CLEN;
    for (int i = d; i < CLEN * 2 * DS; i += 256) {
        int r = i >> 5, j = i & 31;
        float v = g_dbl[(long)(m0 + r) * DBLW + DTR + j];
        if (j < DS) sB[r][j] = v; else sC[r][j - DS] = v;
    }
    float a[DS];
    const float* Ap = Alog + ((long)(nb * NL + l) * DI + d) * DS;
#pragma unroll
    for (int s = 0; s < DS; s++) a[s] = -expf(Ap[s]);
    float A0 = a[0];
    bool ok = true;
#pragma unroll
    for (int s = 0; s < DS; s++)
        ok = ok && (fabsf(a[s] - (float)(s + 1) * A0) <= 1e-4f * fabsf(a[s]) + 1e-7f);
    float Dp = Dpar[(nb * NL + l) * DI + d];
    long off = ((long)(c * NBB + nbb) * DI + d) * DS;
    float h[DS];
#pragma unroll
    for (int s4 = 0; s4 < 4; s4++) {
        float4 cv = *(const float4*)(g_cry + off + s4 * 4);
        h[s4*4] = cv.x; h[s4*4+1] = cv.y; h[s4*4+2] = cv.z; h[s4*4+3] = cv.w;
    }
    __syncthreads();
    if (ok) {
        for (int t = 0; t < CLEN; t++) {
            int mr = m0 + t;
            float dtv = g_dt[(long)mr * DI + d];
            float xcv = g_xc[(long)mr * DI + d];
            float w = dtv * xcv;
            float p = __expf(dtv * A0);
            float cum = 1.f, y = 0.f;
#pragma unroll
            for (int s = 0; s < DS; s++) {
                cum *= p;
                h[s] = fmaf(cum, h[s], w * sB[t][s]);
                y = fmaf(h[s], sC[t][s], y);
            }
            float yf = fmaf(Dp, xcv, y);
            float zv = g_xz[(long)mr * (2 * DI) + DI + d];
            g_ymb[(long)mr * DI + d] = __float2bfloat16(yf * siluf(zv));
        }
    } else {
        for (int t = 0; t < CLEN; t++) {
            int mr = m0 + t;
            float dtv = g_dt[(long)mr * DI + d];
            float xcv = g_xc[(long)mr * DI + d];
            float w = dtv * xcv;
            float y = 0.f;
#pragma unroll
            for (int s = 0; s < DS; s++) {
                float dA = __expf(dtv * a[s]);
                h[s] = fmaf(dA, h[s], w * sB[t][s]);
                y = fmaf(h[s], sC[t][s], y);
            }
            float yf = fmaf(Dp, xcv, y);
            float zv = g_xz[(long)mr * (2 * DI) + DI + d];
            g_ymb[(long)mr * DI + d] = __float2bfloat16(yf * siluf(zv));
        }
    }
}

// ---------------- mean pool over T (2-stage) --------------------------------
__global__ void k_pool1() {
    int nbb = blockIdx.x, ch = blockIdx.y, dm = threadIdx.x;
    long base = ((long)nbb * TT + ch * 128) * DM + dm;
    float s0 = 0.f, s1 = 0.f, s2 = 0.f, s3 = 0.f;
#pragma unroll 4
    for (int t = 0; t < 128; t += 4) {
        s0 += g_h[base + (long)(t + 0) * DM];
        s1 += g_h[base + (long)(t + 1) * DM];
        s2 += g_h[base + (long)(t + 2) * DM];
        s3 += g_h[base + (long)(t + 3) * DM];
    }
    g_poolp[(nbb * 8 + ch) * DM + dm] = (s0 + s1) + (s2 + s3);
}
__global__ void k_pool2() {
    int idx = blockIdx.x * blockDim.x + threadIdx.x;
    if (idx >= NBB * DM) return;
    int nbb = idx / DM, dm = idx - nbb * DM;
    float s = 0.f;
#pragma unroll
    for (int ch = 0; ch < 8; ch++) s += g_poolp[(nbb * 8 + ch) * DM + dm];
    g_pool[idx] = s * (1.f / (float)TT);
}

// ---------------- final: output proj + Lorentz geometry --------------------
__global__ void __launch_bounds__(512)
k_final(const float* __restrict__ Wop, const float* __restrict__ bop,
        const float* __restrict__ eff, float* __restrict__ out) {
    __shared__ float s_us[NBB][EMB];
    int tid = threadIdx.x, w = tid >> 5, lane = tid & 31;
    int nb = w >> 2, b = w & 3;
    int c0 = lane, c1 = lane + 32;
    float es = tanhf(eff[0]);

    float z0 = bop[nb * EMB + c0];
    float z1 = bop[nb * EMB + c1];
    const float* pl = g_pool + w * DM;
    const float* wp = Wop + (long)nb * DM * EMB;
    for (int k = 0; k < DM; k++) {
        float pv = pl[k];
        z0 = fmaf(pv, wp[k * EMB + c0], z0);
        z1 = fmaf(pv, wp[k * EMB + c1], z1);
    }
    out[nb * (BB * EMB) + b * EMB + c0] = z0;
    out[nb * (BB * EMB) + b * EMB + c1] = z1;

    float v0 = z0 * es, v1 = z1 * es;
    float n2 = warpsum(v0 * v0 + v1 * v1);
    float n  = sqrtf(n2);
    float ncv = fminf(fmaxf(n, EPSV), MAXN);
    float sc  = ncv / fmaxf(n, EPSV);
    v0 *= sc; v1 *= sc;
    float shc = sinhf(ncv) / ncv;
    float sp0 = shc * v0, sp1 = shc * v1;
    float sp2 = warpsum(sp0 * sp0 + sp1 * sp1);
    float tproj = sqrtf(1.f + sp2);
    const int zhb = NBR * BB * EMB;
    float* oh = out + zhb + nb * (BB * 65) + b * 65;
    if (lane == 0) oh[0] = tproj;
    oh[1 + c0] = sp0;
    oh[1 + c1] = sp1;

    float ttv = fmaxf(tproj, 1.f + EPSV);
    float dd  = acoshf(ttv);
    float spn = fmaxf(sqrtf(sp2), EPSV);
    float rr  = dd / spn;
    s_us[w][c0] = rr * sp0;
    s_us[w][c1] = rr * sp1;
    __syncthreads();

    if (w < BB) {
        int b2 = w;
        float u0 = 0.f, u1 = 0.f;
#pragma unroll
        for (int q = 0; q < NBR; q++) {
            u0 += s_us[q * BB + b2][c0];
            u1 += s_us[q * BB + b2][c1];
        }
        const int ctb = zhb + NBR * BB * 65;
        out[ctb + b2 * EMB + c0] = u0;
        out[ctb + b2 * EMB + c1] = u1;
        float w0 = u0 * es, w1 = u1 * es;
        float m2 = warpsum(w0 * w0 + w1 * w1);
        float mn = sqrtf(m2);
        float mc = fminf(fmaxf(mn, EPSV), MAXN);
        float ms = mc / fmaxf(mn, EPSV);
        w0 *= ms; w1 *= ms;
        float msh = sinhf(mc) / mc;
        float q0 = msh * w0, q1 = msh * w1;
        float q2 = warpsum(q0 * q0 + q1 * q1);
        float t2 = sqrtf(1.f + q2);
        const int chb = ctb + BB * EMB;
        float* oc = out + chb + b2 * 65;
        if (lane == 0) oc[0] = t2;
        oc[1 + c0] = q0;
        oc[1 + c1] = q1;
    }
}

// ---------------------------------------------------------------------------
extern "C" void kernel_launch(void* const* d_in, const int* in_sizes, int n_in,
                              void* d_out, int out_size) {
    const float* x0   = (const float*)d_in[0];
    const float* x1   = (const float*)d_in[1];
    const float* x2   = (const float*)d_in[2];
    const float* x3   = (const float*)d_in[3];
    const float* Wip  = (const float*)d_in[4];
    const float* bip  = (const float*)d_in[5];
    const float* Win  = (const float*)d_in[6];
    const float* cw   = (const float*)d_in[7];
    const float* cb   = (const float*)d_in[8];
    const float* Wx   = (const float*)d_in[9];
    const float* Wdt  = (const float*)d_in[10];
    const float* bdt  = (const float*)d_in[11];
    const float* Alog = (const float*)d_in[12];
    const float* Dpar = (const float*)d_in[13];
    const float* Wout = (const float*)d_in[14];
    const float* Wop  = (const float*)d_in[15];
    const float* bop  = (const float*)d_in[16];
    const float* eff  = (const float*)d_in[17];
    float* out = (float*)d_out;

    __nv_bfloat16 *p_hb, *p_xcb, *p_ymb, *p_WinT, *p_WxT, *p_WoutT;
    float *p_xz, *p_dbl, *p_h;
    cudaGetSymbolAddress((void**)&p_hb,    g_hb);
    cudaGetSymbolAddress((void**)&p_xcb,   g_xcb);
    cudaGetSymbolAddress((void**)&p_ymb,   g_ymb);
    cudaGetSymbolAddress((void**)&p_WinT,  g_WinT);
    cudaGetSymbolAddress((void**)&p_WxT,   g_WxT);
    cudaGetSymbolAddress((void**)&p_WoutT, g_WoutT);
    cudaGetSymbolAddress((void**)&p_xz,    g_xz);
    cudaGetSymbolAddress((void**)&p_dbl,   g_dbl);
    cudaGetSymbolAddress((void**)&p_h,     g_h);

    const int SM_G1 = (128 + 128) * (128 + 8) * 2; // 69632
    const int SM_G2 = (64 + 64)   * (256 + 8) * 2; // 67584
    const int SM_G3 = (64 + 128)  * (256 + 8) * 2; // 101376
    cudaFuncSetAttribute(k_hmma<128,128,128,0>, cudaFuncAttributeMaxDynamicSharedMemorySize, SM_G1);
    cudaFuncSetAttribute(k_hmma<64,64,256,1>,   cudaFuncAttributeMaxDynamicSharedMemorySize, SM_G2);
    cudaFuncSetAttribute(k_hmma<64,128,256,2>,  cudaFuncAttributeMaxDynamicSharedMemorySize, SM_G3);

    // coalesced weight transposes
    k_tr<128, 512, 512><<<dim3(16, 4, NBR*NL), dim3(32, 8)>>>(Win,  p_WinT);
    k_tr<256, 40,  64 ><<<dim3(2,  8, NBR*NL), dim3(32, 8)>>>(Wx,   p_WxT);
    k_tr<256, 128, 128><<<dim3(4,  8, NBR*NL), dim3(32, 8)>>>(Wout, p_WoutT);

    k_inproj<<<(ROWS * DM) / 256, 256>>>(x0, x1, x2, x3, Wip, bip);

    for (int l = 0; l < NL; l++) {
        // xz = h @ W_in[:,l]   (M=4096, N=512, K=128) per branch
        k_hmma<128,128,128,0><<<dim3(4, RPB/128, NBR), 256, SM_G1>>>(
            p_hb, p_WinT + (long)l*512*128, p_xz, nullptr,
            512, (long)RPB*128, (long)NL*512*128, (long)RPB*512);

        k_conv<<<((ROWS/4) * 64) / 256, 256>>>(cw, cb, l);

        // dbl = xc @ W_x[:,l]  (N=40 padded 64, K=256)
        k_hmma<64,64,256,1><<<dim3(1, RPB/64, NBR), 256, SM_G2>>>(
            p_xcb, p_WxT + (long)l*64*256, p_dbl, nullptr,
            DBLW, (long)RPB*256, (long)NL*64*256, (long)RPB*DBLW);

        k_scan1<<<dim3(CHUNKS, NBB), 256>>>(Alog, Wdt, bdt, l);
        k_carry<<<(NBB * DI * DS) / 256, 256>>>();
        k_scan3<<<dim3(CHUNKS, NBB), 256>>>(Alog, Dpar, l);

        // h = ym @ W_out[:,l]  (N=128, K=256), f32 + bf16 outputs
        k_hmma<64,128,256,2><<<dim3(1, RPB/64, NBR), 256, SM_G3>>>(
            p_ymb, p_WoutT + (long)l*128*256, p_h, p_hb,
            DM, (long)RPB*256, (long)NL*128*256, (long)RPB*DM);
    }

    k_pool1<<<dim3(NBB, 8), DM>>>();
    k_pool2<<<(NBB * DM + 127) / 128, 128>>>();
    k_final<<<1, 512>>>(Wop, bop, eff, out);
}

// round 9
// speedup vs baseline: 2.3149x; 1.0520x over previous
#include <cuda_runtime.h>
#include <cuda_bf16.h>
#include <math.h>
#include <stdint.h>

#define NBR 4
#define NL  3
#define BB  4
#define TT  1024
#define DIN 32
#define DM  128
#define DI  256
#define DS  16
#define DC  4
#define DTR 8
#define EMB 64
#define ROWS (NBR*BB*TT)   /* 16384 */
#define RPB  (BB*TT)       /* 4096  */
#define NBB  (NBR*BB)      /* 16    */
#define CHUNKS 32
#define CLEN (TT/CHUNKS)   /* 32    */
#define DBLW (DTR+2*DS)    /* 40    */
#define EPSV 1e-7f
#define MAXN 10.0f

// ---------------- scratch (static device memory; no allocs) ----------------
__device__ float          g_h    [ROWS*DM];
__device__ __nv_bfloat16  g_hb   [ROWS*DM];
__device__ __nv_bfloat16  g_xzb  [ROWS*2*DI];
__device__ __nv_bfloat16  g_xcb  [ROWS*DI];
__device__ float          g_dbl  [ROWS*DBLW];
__device__ __nv_bfloat16  g_ymb  [ROWS*DI];
__device__ float g_hend [CHUNKS*NBB*DI*DS];
__device__ float g_P    [CHUNKS*NBB*DI*DS];
__device__ float g_cry  [CHUNKS*NBB*DI*DS];
__device__ float g_poolp[NBB*8*DM];
// transposed bf16 weights: [br][l][N][K]
__device__ __nv_bfloat16 g_WinT [NBR*NL*512*128];
__device__ __nv_bfloat16 g_WxT  [NBR*NL*64*256];   // N padded 40->64 (zeros)
__device__ __nv_bfloat16 g_WoutT[NBR*NL*128*256];

__device__ __forceinline__ float warpsum(float v) {
#pragma unroll
    for (int o = 16; o > 0; o >>= 1) v += __shfl_xor_sync(0xffffffffu, v, o);
    return v;
}
__device__ __forceinline__ float siluf(float x) { return x / (1.f + __expf(-x)); }

// ---------------- HMMA 16x8x16 bf16 (baseline PTX, works on compute_103) ---
__device__ __forceinline__ void mma16816(float* d, const uint32_t* a, const uint32_t* b) {
    asm volatile(
        "mma.sync.aligned.m16n8k16.row.col.f32.bf16.bf16.f32 "
        "{%0,%1,%2,%3}, {%4,%5,%6,%7}, {%8,%9}, {%0,%1,%2,%3};"
        : "+f"(d[0]), "+f"(d[1]), "+f"(d[2]), "+f"(d[3])
        : "r"(a[0]), "r"(a[1]), "r"(a[2]), "r"(a[3]), "r"(b[0]), "r"(b[1]));
}

// ---------------- coalesced transpose + bf16 convert: [K,N] -> [NPAD,K] ----
template<int KD, int ND, int NPAD>
__global__ void k_tr(const float* __restrict__ W, __nv_bfloat16* __restrict__ out) {
    __shared__ float tile[32][33];
    int mIdx = blockIdx.z;
    const float* Wm = W + (long)mIdx * KD * ND;
    __nv_bfloat16* om = out + (long)mIdx * NPAD * KD;
    int n0 = blockIdx.x * 32, k0 = blockIdx.y * 32;
    int tx = threadIdx.x, ty = threadIdx.y;   // 32 x 8
#pragma unroll
    for (int i = 0; i < 32; i += 8) {
        int k = k0 + ty + i, n = n0 + tx;
        tile[ty + i][tx] = (n < ND) ? Wm[(long)k * ND + n] : 0.f;
    }
    __syncthreads();
#pragma unroll
    for (int i = 0; i < 32; i += 8) {
        int n = n0 + ty + i, k = k0 + tx;
        if (n < NPAD) om[(long)n * KD + k] = __float2bfloat16(tile[tx][ty + i]);
    }
}

// ---------------- HMMA GEMM: C[M,N] = A[M,K] @ Bt[N,K]^T (batched over z) --
// MODE 1: f32 store cols<40   MODE 2: f32 + bf16 store   MODE 3: bf16 only
template<int BM, int BN, int K, int MODE>
__global__ void __launch_bounds__(256, 1)
k_hmma(const __nv_bfloat16* __restrict__ A, const __nv_bfloat16* __restrict__ Bt,
       float* __restrict__ C, __nv_bfloat16* __restrict__ Cb,
       int Nld, long strA, long strB, long strC) {
    constexpr int LDK  = K + 8;
    constexpr int LDKU = LDK / 2;
    constexpr int WARPS_M = BM / 32;
    constexpr int WN = BN / (8 / WARPS_M);
    constexpr int NT = WN / 8;
    constexpr int K8 = K / 8;

    extern __shared__ __align__(16) char smem[];
    __nv_bfloat16* shA = (__nv_bfloat16*)smem;
    __nv_bfloat16* shB = shA + BM * LDK;

    int tid = threadIdx.x;
    int rowBase = blockIdx.y * BM;
    int colBase = blockIdx.x * BN;
    const __nv_bfloat16* Ap = A  + (long)blockIdx.z * strA + (long)rowBase * K;
    const __nv_bfloat16* Bp = Bt + (long)blockIdx.z * strB + (long)colBase * K;
    float* Cp = (MODE != 3) ? (C + (long)blockIdx.z * strC) : nullptr;
    __nv_bfloat16* Cbp = (MODE >= 2) ? (Cb + (long)blockIdx.z * strC) : nullptr;

#pragma unroll 4
    for (int idx = tid; idx < BM * K8; idx += 256) {
        int r = idx / K8, c8 = idx - r * K8;
        *(uint4*)(shA + r * LDK + c8 * 8) = *(const uint4*)(Ap + (long)r * K + c8 * 8);
    }
#pragma unroll 4
    for (int idx = tid; idx < BN * K8; idx += 256) {
        int r = idx / K8, c8 = idx - r * K8;
        *(uint4*)(shB + r * LDK + c8 * 8) = *(const uint4*)(Bp + (long)r * K + c8 * 8);
    }
    __syncthreads();

    int w = tid >> 5, lane = tid & 31;
    int gid = lane >> 2, tig = lane & 3;
    int wm = w % WARPS_M, wn = w / WARPS_M;
    const uint32_t* sAu = (const uint32_t*)shA;
    const uint32_t* sBu = (const uint32_t*)shB;

    float acc[2][NT][4];
#pragma unroll
    for (int mt = 0; mt < 2; mt++)
#pragma unroll
        for (int nt = 0; nt < NT; nt++)
#pragma unroll
            for (int i = 0; i < 4; i++) acc[mt][nt][i] = 0.f;

    int aRow0 = wm * 32 + gid;
    int bRow0 = wn * WN + gid;

#pragma unroll
    for (int kt = 0; kt < K / 16; kt++) {
        int kb2 = kt * 8 + tig;
        uint32_t afr[2][4];
#pragma unroll
        for (int mt = 0; mt < 2; mt++) {
            int r0 = aRow0 + mt * 16;
            afr[mt][0] = sAu[r0 * LDKU + kb2];
            afr[mt][1] = sAu[(r0 + 8) * LDKU + kb2];
            afr[mt][2] = sAu[r0 * LDKU + kb2 + 4];
            afr[mt][3] = sAu[(r0 + 8) * LDKU + kb2 + 4];
        }
        uint32_t bfr[NT][2];
#pragma unroll
        for (int nt = 0; nt < NT; nt++) {
            int rb = bRow0 + nt * 8;
            bfr[nt][0] = sBu[rb * LDKU + kb2];
            bfr[nt][1] = sBu[rb * LDKU + kb2 + 4];
        }
#pragma unroll
        for (int mt = 0; mt < 2; mt++)
#pragma unroll
            for (int nt = 0; nt < NT; nt++)
                mma16816(acc[mt][nt], afr[mt], bfr[nt]);
    }

#pragma unroll
    for (int mt = 0; mt < 2; mt++) {
#pragma unroll
        for (int nt = 0; nt < NT; nt++) {
            int r0 = rowBase + wm * 32 + mt * 16 + gid;
            int c0 = colBase + wn * WN + nt * 8 + 2 * tig;
            if (MODE == 1 && c0 >= 40) continue;
            float2 v0 = make_float2(acc[mt][nt][0], acc[mt][nt][1]);
            float2 v1 = make_float2(acc[mt][nt][2], acc[mt][nt][3]);
            if (MODE != 3) {
                *(float2*)(Cp + (long)r0 * Nld + c0) = v0;
                *(float2*)(Cp + (long)(r0 + 8) * Nld + c0) = v1;
            }
            if (MODE >= 2) {
                *(__nv_bfloat162*)(Cbp + (long)r0 * Nld + c0) =
                    __floats2bfloat162_rn(v0.x, v0.y);
                *(__nv_bfloat162*)(Cbp + (long)(r0 + 8) * Nld + c0) =
                    __floats2bfloat162_rn(v1.x, v1.y);
            }
        }
    }
}

// ---------------- input projection: hb = bf16(x @ W_ip + b_ip) -------------
// one thread -> 4 outputs (dm..dm+3), float4 loads both operands
__global__ void __launch_bounds__(256)
k_inproj(const float* __restrict__ x0, const float* __restrict__ x1,
         const float* __restrict__ x2, const float* __restrict__ x3,
         const float* __restrict__ Wip, const float* __restrict__ bip) {
    int gid = blockIdx.x * blockDim.x + threadIdx.x;
    if (gid >= ROWS * 32) return;
    int q  = gid & 31;
    int m  = gid >> 5;
    int d0 = q * 4;
    int nb = m / RPB;
    int r  = m - nb * RPB;
    const float* x = (nb == 0) ? x0 : (nb == 1) ? x1 : (nb == 2) ? x2 : x3;
    const float* xr = x + r * DIN;
    const float* w  = Wip + nb * DIN * DM + d0;
    float4 acc = *(const float4*)(bip + nb * DM + d0);
#pragma unroll
    for (int k8 = 0; k8 < DIN; k8 += 4) {
        float4 xv = *(const float4*)(xr + k8);
#pragma unroll
        for (int j = 0; j < 4; j++) {
            float xs = (j == 0) ? xv.x : (j == 1) ? xv.y : (j == 2) ? xv.z : xv.w;
            float4 wv = *(const float4*)(w + (k8 + j) * DM);
            acc.x = fmaf(xs, wv.x, acc.x);
            acc.y = fmaf(xs, wv.y, acc.y);
            acc.z = fmaf(xs, wv.z, acc.z);
            acc.w = fmaf(xs, wv.w, acc.w);
        }
    }
    __nv_bfloat162* ob = (__nv_bfloat162*)(g_hb + (long)m * DM + d0);
    ob[0] = __floats2bfloat162_rn(acc.x, acc.y);
    ob[1] = __floats2bfloat162_rn(acc.z, acc.w);
}

// ---------------- causal depthwise conv + SiLU (8 timesteps / thread) ------
__global__ void __launch_bounds__(256)
k_conv(const float* __restrict__ cw, const float* __restrict__ cb, int l) {
    int gid = blockIdx.x * blockDim.x + threadIdx.x;
    if (gid >= (ROWS / 8) * 64) return;
    int q  = gid & 63;            // channel group (4 channels)
    int m8 = gid >> 6;            // group of 8 rows
    int d0 = q * 4;
    int nb = m8 / (RPB / 8);
    int t0 = (m8 & (TT / 8 - 1)) * 8;
    int mrow = m8 * 8;

    const float* cwp = cw + (((long)(nb * NL + l)) * DI + d0) * DC;
    float cwa[16];
    *(float4*)(cwa + 0)  = *(const float4*)(cwp + 0);
    *(float4*)(cwa + 4)  = *(const float4*)(cwp + 4);
    *(float4*)(cwa + 8)  = *(const float4*)(cwp + 8);
    *(float4*)(cwa + 12) = *(const float4*)(cwp + 12);
    const float* cbp = cb + (long)(nb * NL + l) * DI + d0;
    float4 bias = *(const float4*)cbp;

    float4 xr[11];
#pragma unroll
    for (int j = 0; j < 11; j++) {
        int tr = t0 + j - 3;
        if (tr >= 0) {
            __nv_bfloat162 b01 = *(const __nv_bfloat162*)(g_xzb + (long)(mrow + j - 3) * (2 * DI) + d0);
            __nv_bfloat162 b23 = *(const __nv_bfloat162*)(g_xzb + (long)(mrow + j - 3) * (2 * DI) + d0 + 2);
            float2 f01 = __bfloat1622float2(b01);
            float2 f23 = __bfloat1622float2(b23);
            xr[j] = make_float4(f01.x, f01.y, f23.x, f23.y);
        } else {
            xr[j] = make_float4(0.f, 0.f, 0.f, 0.f);
        }
    }
#pragma unroll
    for (int i = 0; i < 8; i++) {
        float a0 = bias.x, a1 = bias.y, a2 = bias.z, a3 = bias.w;
#pragma unroll
        for (int k = 0; k < DC; k++) {
            float4 xv = xr[i + k];
            a0 = fmaf(xv.x, cwa[0 * DC + k], a0);
            a1 = fmaf(xv.y, cwa[1 * DC + k], a1);
            a2 = fmaf(xv.z, cwa[2 * DC + k], a2);
            a3 = fmaf(xv.w, cwa[3 * DC + k], a3);
        }
        long row = mrow + i;
        __nv_bfloat162* xb = (__nv_bfloat162*)(g_xcb + row * DI + d0);
        xb[0] = __floats2bfloat162_rn(siluf(a0), siluf(a1));
        xb[1] = __floats2bfloat162_rn(siluf(a2), siluf(a3));
    }
}

// ---------------- scan pass 1: fused dt + per-chunk local scan -------------
__global__ void __launch_bounds__(256)
k_scan1(const float* __restrict__ Alog, const float* __restrict__ Wdt,
        const float* __restrict__ bdt, int l) {
    int c = blockIdx.x, nbb = blockIdx.y, d = threadIdx.x, nb = nbb >> 2;
    __shared__ float sD[CLEN][DTR];
    __shared__ float sB[CLEN][DS];
    int m0 = nbb * TT + c * CLEN;
    for (int i = d; i < CLEN * (DTR + DS); i += 256) {
        int r = i / (DTR + DS), j = i - r * (DTR + DS);
        float v = g_dbl[(long)(m0 + r) * DBLW + j];
        if (j < DTR) sD[r][j] = v; else sB[r][j - DTR] = v;
    }
    float a[DS];
    const float* Ap = Alog + ((long)(nb * NL + l) * DI + d) * DS;
#pragma unroll
    for (int s = 0; s < DS; s++) a[s] = -expf(Ap[s]);
    float A0 = a[0];
    bool ok = true;
#pragma unroll
    for (int s = 0; s < DS; s++)
        ok = ok && (fabsf(a[s] - (float)(s + 1) * A0) <= 1e-4f * fabsf(a[s]) + 1e-7f);
    float wdt[DTR];
    const float* wdp = Wdt + (long)(nb * NL + l) * DTR * DI + d;
#pragma unroll
    for (int r = 0; r < DTR; r++) wdt[r] = wdp[r * DI];
    float bdtv = bdt[(nb * NL + l) * DI + d];
    __syncthreads();

    float h[DS], P[DS];
#pragma unroll
    for (int s = 0; s < DS; s++) { h[s] = 0.f; P[s] = 1.f; }
    if (ok) {
        for (int t = 0; t < CLEN; t++) {
            int mr = m0 + t;
            float u = bdtv;
#pragma unroll
            for (int r = 0; r < DTR; r++) u = fmaf(sD[t][r], wdt[r], u);
            float dtv = (u > 20.f) ? u : __logf(1.f + __expf(u));
            float xcv = __bfloat162float(g_xcb[(long)mr * DI + d]);
            float w = dtv * xcv;
            float p = __expf(dtv * A0);
            float cum = 1.f;
#pragma unroll
            for (int s = 0; s < DS; s++) {
                cum *= p;
                h[s] = fmaf(cum, h[s], w * sB[t][s]);
                P[s] *= cum;
            }
        }
    } else {
        for (int t = 0; t < CLEN; t++) {
            int mr = m0 + t;
            float u = bdtv;
#pragma unroll
            for (int r = 0; r < DTR; r++) u = fmaf(sD[t][r], wdt[r], u);
            float dtv = (u > 20.f) ? u : __logf(1.f + __expf(u));
            float xcv = __bfloat162float(g_xcb[(long)mr * DI + d]);
            float w = dtv * xcv;
#pragma unroll
            for (int s = 0; s < DS; s++) {
                float dA = __expf(dtv * a[s]);
                h[s] = fmaf(dA, h[s], w * sB[t][s]);
                P[s] *= dA;
            }
        }
    }
    long off = ((long)(c * NBB + nbb) * DI + d) * DS;
    float4* he = (float4*)(g_hend + off);
    float4* pe = (float4*)(g_P + off);
#pragma unroll
    for (int s4 = 0; s4 < 4; s4++) {
        he[s4] = make_float4(h[s4*4], h[s4*4+1], h[s4*4+2], h[s4*4+3]);
        pe[s4] = make_float4(P[s4*4], P[s4*4+1], P[s4*4+2], P[s4*4+3]);
    }
}

// ---------------- scan pass 2: combine carries across chunks ---------------
__global__ void k_carry() {
    int idx = blockIdx.x * blockDim.x + threadIdx.x;
    if (idx >= NBB * DI * DS) return;
    float h = 0.f;
#pragma unroll
    for (int c = 0; c < CHUNKS; c++) {
        long off = (long)c * (NBB * DI * DS) + idx;
        g_cry[off] = h;
        h = fmaf(g_P[off], h, g_hend[off]);
    }
}

// ---------------- scan pass 3: full scan + fused epilogue (bf16 ym) --------
__global__ void __launch_bounds__(256)
k_scan3(const float* __restrict__ Alog, const float* __restrict__ Wdt,
        const float* __restrict__ bdt, const float* __restrict__ Dpar, int l) {
    int c = blockIdx.x, nbb = blockIdx.y, d = threadIdx.x, nb = nbb >> 2;
    __shared__ float sD[CLEN][DTR];
    __shared__ float sB[CLEN][DS];
    __shared__ float sC[CLEN][DS];
    int m0 = nbb * TT + c * CLEN;
    for (int i = d; i < CLEN * DBLW; i += 256) {
        int r = i / DBLW, j = i - r * DBLW;
        float v = g_dbl[(long)(m0 + r) * DBLW + j];
        if (j < DTR) sD[r][j] = v;
        else if (j < DTR + DS) sB[r][j - DTR] = v;
        else sC[r][j - DTR - DS] = v;
    }
    float a[DS];
    const float* Ap = Alog + ((long)(nb * NL + l) * DI + d) * DS;
#pragma unroll
    for (int s = 0; s < DS; s++) a[s] = -expf(Ap[s]);
    float A0 = a[0];
    bool ok = true;
#pragma unroll
    for (int s = 0; s < DS; s++)
        ok = ok && (fabsf(a[s] - (float)(s + 1) * A0) <= 1e-4f * fabsf(a[s]) + 1e-7f);
    float wdt[DTR];
    const float* wdp = Wdt + (long)(nb * NL + l) * DTR * DI + d;
#pragma unroll
    for (int r = 0; r < DTR; r++) wdt[r] = wdp[r * DI];
    float bdtv = bdt[(nb * NL + l) * DI + d];
    float Dp = Dpar[(nb * NL + l) * DI + d];
    long off = ((long)(c * NBB + nbb) * DI + d) * DS;
    float h[DS];
#pragma unroll
    for (int s4 = 0; s4 < 4; s4++) {
        float4 cv = *(const float4*)(g_cry + off + s4 * 4);
        h[s4*4] = cv.x; h[s4*4+1] = cv.y; h[s4*4+2] = cv.z; h[s4*4+3] = cv.w;
    }
    __syncthreads();
    if (ok) {
        for (int t = 0; t < CLEN; t++) {
            int mr = m0 + t;
            float u = bdtv;
#pragma unroll
            for (int r = 0; r < DTR; r++) u = fmaf(sD[t][r], wdt[r], u);
            float dtv = (u > 20.f) ? u : __logf(1.f + __expf(u));
            float xcv = __bfloat162float(g_xcb[(long)mr * DI + d]);
            float w = dtv * xcv;
            float p = __expf(dtv * A0);
            float cum = 1.f, y = 0.f;
#pragma unroll
            for (int s = 0; s < DS; s++) {
                cum *= p;
                h[s] = fmaf(cum, h[s], w * sB[t][s]);
                y = fmaf(h[s], sC[t][s], y);
            }
            float yf = fmaf(Dp, xcv, y);
            float zv = __bfloat162float(g_xzb[(long)mr * (2 * DI) + DI + d]);
            g_ymb[(long)mr * DI + d] = __float2bfloat16(yf * siluf(zv));
        }
    } else {
        for (int t = 0; t < CLEN; t++) {
            int mr = m0 + t;
            float u = bdtv;
#pragma unroll
            for (int r = 0; r < DTR; r++) u = fmaf(sD[t][r], wdt[r], u);
            float dtv = (u > 20.f) ? u : __logf(1.f + __expf(u));
            float xcv = __bfloat162float(g_xcb[(long)mr * DI + d]);
            float w = dtv * xcv;
            float y = 0.f;
#pragma unroll
            for (int s = 0; s < DS; s++) {
                float dA = __expf(dtv * a[s]);
                h[s] = fmaf(dA, h[s], w * sB[t][s]);
                y = fmaf(h[s], sC[t][s], y);
            }
            float yf = fmaf(Dp, xcv, y);
            float zv = __bfloat162float(g_xzb[(long)mr * (2 * DI) + DI + d]);
            g_ymb[(long)mr * DI + d] = __float2bfloat16(yf * siluf(zv));
        }
    }
}

// ---------------- mean pool over T (stage 1) --------------------------------
__global__ void k_pool1() {
    int nbb = blockIdx.x, ch = blockIdx.y, dm = threadIdx.x;
    long base = ((long)nbb * TT + ch * 128) * DM + dm;
    float s0 = 0.f, s1 = 0.f, s2 = 0.f, s3 = 0.f;
#pragma unroll 4
    for (int t = 0; t < 128; t += 4) {
        s0 += g_h[base + (long)(t + 0) * DM];
        s1 += g_h[base + (long)(t + 1) * DM];
        s2 += g_h[base + (long)(t + 2) * DM];
        s3 += g_h[base + (long)(t + 3) * DM];
    }
    g_poolp[(nbb * 8 + ch) * DM + dm] = (s0 + s1) + (s2 + s3);
}

// ---------------- final: pool combine + output proj + Lorentz geometry -----
__global__ void __launch_bounds__(512)
k_final(const float* __restrict__ Wop, const float* __restrict__ bop,
        const float* __restrict__ eff, float* __restrict__ out) {
    __shared__ float s_pool[NBB][DM];
    __shared__ float s_us[NBB][EMB];
    int tid = threadIdx.x, w = tid >> 5, lane = tid & 31;
    int nb = w >> 2, b = w & 3;
    int c0 = lane, c1 = lane + 32;

    for (int idx = tid; idx < NBB * DM; idx += 512) {
        int p = idx >> 7, dm = idx & 127;
        float s = 0.f;
#pragma unroll
        for (int ch = 0; ch < 8; ch++) s += g_poolp[(p * 8 + ch) * DM + dm];
        s_pool[p][dm] = s * (1.f / (float)TT);
    }
    __syncthreads();

    float es = tanhf(eff[0]);
    float z0 = bop[nb * EMB + c0];
    float z1 = bop[nb * EMB + c1];
    const float* pl = s_pool[w];
    const float* wp = Wop + (long)nb * DM * EMB;
    for (int k = 0; k < DM; k++) {
        float pv = pl[k];
        z0 = fmaf(pv, wp[k * EMB + c0], z0);
        z1 = fmaf(pv, wp[k * EMB + c1], z1);
    }
    out[nb * (BB * EMB) + b * EMB + c0] = z0;
    out[nb * (BB * EMB) + b * EMB + c1] = z1;

    float v0 = z0 * es, v1 = z1 * es;
    float n2 = warpsum(v0 * v0 + v1 * v1);
    float n  = sqrtf(n2);
    float ncv = fminf(fmaxf(n, EPSV), MAXN);
    float sc  = ncv / fmaxf(n, EPSV);
    v0 *= sc; v1 *= sc;
    float shc = sinhf(ncv) / ncv;
    float sp0 = shc * v0, sp1 = shc * v1;
    float sp2 = warpsum(sp0 * sp0 + sp1 * sp1);
    float tproj = sqrtf(1.f + sp2);
    const int zhb = NBR * BB * EMB;
    float* oh = out + zhb + nb * (BB * 65) + b * 65;
    if (lane == 0) oh[0] = tproj;
    oh[1 + c0] = sp0;
    oh[1 + c1] = sp1;

    float ttv = fmaxf(tproj, 1.f + EPSV);
    float dd  = acoshf(ttv);
    float spn = fmaxf(sqrtf(sp2), EPSV);
    float rr  = dd / spn;
    s_us[w][c0] = rr * sp0;
    s_us[w][c1] = rr * sp1;
    __syncthreads();

    if (w < BB) {
        int b2 = w;
        float u0 = 0.f, u1 = 0.f;
#pragma unroll
        for (int q = 0; q < NBR; q++) {
            u0 += s_us[q * BB + b2][c0];
            u1 += s_us[q * BB + b2][c1];
        }
        const int ctb = zhb + NBR * BB * 65;
        out[ctb + b2 * EMB + c0] = u0;
        out[ctb + b2 * EMB + c1] = u1;
        float w0 = u0 * es, w1 = u1 * es;
        float m2 = warpsum(w0 * w0 + w1 * w1);
        float mn = sqrtf(m2);
        float mc = fminf(fmaxf(mn, EPSV), MAXN);
        float ms = mc / fmaxf(mn, EPSV);
        w0 *= ms; w1 *= ms;
        float msh = sinhf(mc) / mc;
        float q0 = msh * w0, q1 = msh * w1;
        float q2 = warpsum(q0 * q0 + q1 * q1);
        float t2 = sqrtf(1.f + q2);
        const int chb = ctb + BB * EMB;
        float* oc = out + chb + b2 * 65;
        if (lane == 0) oc[0] = t2;
        oc[1 + c0] = q0;
        oc[1 + c1] = q1;
    }
}

// ---------------------------------------------------------------------------
extern "C" void kernel_launch(void* const* d_in, const int* in_sizes, int n_in,
                              void* d_out, int out_size) {
    const float* x0   = (const float*)d_in[0];
    const float* x1   = (const float*)d_in[1];
    const float* x2   = (const float*)d_in[2];
    const float* x3   = (const float*)d_in[3];
    const float* Wip  = (const float*)d_in[4];
    const float* bip  = (const float*)d_in[5];
    const float* Win  = (const float*)d_in[6];
    const float* cw   = (const float*)d_in[7];
    const float* cb   = (const float*)d_in[8];
    const float* Wx   = (const float*)d_in[9];
    const float* Wdt  = (const float*)d_in[10];
    const float* bdt  = (const float*)d_in[11];
    const float* Alog = (const float*)d_in[12];
    const float* Dpar = (const float*)d_in[13];
    const float* Wout = (const float*)d_in[14];
    const float* Wop  = (const float*)d_in[15];
    const float* bop  = (const float*)d_in[16];
    const float* eff  = (const float*)d_in[17];
    float* out = (float*)d_out;

    __nv_bfloat16 *p_hb, *p_xzb, *p_xcb, *p_ymb, *p_WinT, *p_WxT, *p_WoutT;
    float *p_dbl, *p_h;
    cudaGetSymbolAddress((void**)&p_hb,    g_hb);
    cudaGetSymbolAddress((void**)&p_xzb,   g_xzb);
    cudaGetSymbolAddress((void**)&p_xcb,   g_xcb);
    cudaGetSymbolAddress((void**)&p_ymb,   g_ymb);
    cudaGetSymbolAddress((void**)&p_WinT,  g_WinT);
    cudaGetSymbolAddress((void**)&p_WxT,   g_WxT);
    cudaGetSymbolAddress((void**)&p_WoutT, g_WoutT);
    cudaGetSymbolAddress((void**)&p_dbl,   g_dbl);
    cudaGetSymbolAddress((void**)&p_h,     g_h);

    const int SM_G1 = (128 + 128) * (128 + 8) * 2; // 69632
    const int SM_G2 = (64 + 64)   * (256 + 8) * 2; // 67584
    const int SM_G3 = (64 + 128)  * (256 + 8) * 2; // 101376
    cudaFuncSetAttribute(k_hmma<128,128,128,3>, cudaFuncAttributeMaxDynamicSharedMemorySize, SM_G1);
    cudaFuncSetAttribute(k_hmma<64,64,256,1>,   cudaFuncAttributeMaxDynamicSharedMemorySize, SM_G2);
    cudaFuncSetAttribute(k_hmma<64,128,256,2>,  cudaFuncAttributeMaxDynamicSharedMemorySize, SM_G3);

    // coalesced weight transposes
    k_tr<128, 512, 512><<<dim3(16, 4, NBR*NL), dim3(32, 8)>>>(Win,  p_WinT);
    k_tr<256, 40,  64 ><<<dim3(2,  8, NBR*NL), dim3(32, 8)>>>(Wx,   p_WxT);
    k_tr<256, 128, 128><<<dim3(4,  8, NBR*NL), dim3(32, 8)>>>(Wout, p_WoutT);

    k_inproj<<<(ROWS * 32) / 256, 256>>>(x0, x1, x2, x3, Wip, bip);

    for (int l = 0; l < NL; l++) {
        // xz = h @ W_in[:,l]   (M=4096, N=512, K=128), bf16-only store
        k_hmma<128,128,128,3><<<dim3(4, RPB/128, NBR), 256, SM_G1>>>(
            p_hb, p_WinT + (long)l*512*128, nullptr, p_xzb,
            512, (long)RPB*128, (long)NL*512*128, (long)RPB*512);

        k_conv<<<((ROWS/8) * 64) / 256, 256>>>(cw, cb, l);

        // dbl = xc @ W_x[:,l]  (N=40 padded 64, K=256)
        k_hmma<64,64,256,1><<<dim3(1, RPB/64, NBR), 256, SM_G2>>>(
            p_xcb, p_WxT + (long)l*64*256, p_dbl, nullptr,
            DBLW, (long)RPB*256, (long)NL*64*256, (long)RPB*DBLW);

        k_scan1<<<dim3(CHUNKS, NBB), 256>>>(Alog, Wdt, bdt, l);
        k_carry<<<(NBB * DI * DS) / 256, 256>>>();
        k_scan3<<<dim3(CHUNKS, NBB), 256>>>(Alog, Wdt, bdt, Dpar, l);

        // h = ym @ W_out[:,l]  (N=128, K=256), f32 + bf16 outputs
        k_hmma<64,128,256,2><<<dim3(1, RPB/64, NBR), 256, SM_G3>>>(
            p_ymb, p_WoutT + (long)l*128*256, p_h, p_hb,
            DM, (long)RPB*256, (long)NL*128*256, (long)RPB*DM);
    }

    k_pool1<<<dim3(NBB, 8), DM>>>();
    k_final<<<1, 512>>>(Wop, bop, eff, out);
}

// round 12
// speedup vs baseline: 2.4789x; 1.0709x over previous
#include <cuda_runtime.h>
#include <cuda_bf16.h>
#include <math.h>
#include <stdint.h>

#define NBR 4
#define NL  3
#define BB  4
#define TT  1024
#define DIN 32
#define DM  128
#define DI  256
#define DS  16
#define DC  4
#define DTR 8
#define EMB 64
#define ROWS (NBR*BB*TT)   /* 16384 */
#define RPB  (BB*TT)       /* 4096  */
#define NBB  (NBR*BB)      /* 16    */
#define CHUNKS 32
#define CLEN (TT/CHUNKS)   /* 32    */
#define DBLW (DTR+2*DS)    /* 40    */
#define EPSV 1e-7f
#define MAXN 10.0f

// ---------------- scratch (static device memory; no allocs) ----------------
__device__ __nv_bfloat16  g_xb   [ROWS*DIN];
__device__ __nv_bfloat16  g_hb   [ROWS*DM];
__device__ __nv_bfloat16  g_xzb  [ROWS*2*DI];
__device__ __nv_bfloat16  g_xcb  [ROWS*DI];
__device__ float          g_dbl  [ROWS*DBLW];
__device__ __nv_bfloat16  g_ymb  [ROWS*DI];
__device__ float g_hend [CHUNKS*NBB*DI*DS];
__device__ float g_P    [CHUNKS*NBB*DI*DS];
__device__ float g_cry  [CHUNKS*NBB*DI*DS];
__device__ float g_poolp[NBB*16*DM];
// transposed bf16 weights: [br][l][N][K]
__device__ __nv_bfloat16 g_WipT [NBR*DM*DIN];
__device__ __nv_bfloat16 g_WinT [NBR*NL*512*128];
__device__ __nv_bfloat16 g_WxT  [NBR*NL*64*256];   // N padded 40->64 (zeros)
__device__ __nv_bfloat16 g_WoutT[NBR*NL*128*256];

__device__ __forceinline__ float warpsum(float v) {
#pragma unroll
    for (int o = 16; o > 0; o >>= 1) v += __shfl_xor_sync(0xffffffffu, v, o);
    return v;
}
__device__ __forceinline__ float siluf(float x) { return x / (1.f + __expf(-x)); }

// ---------------- HMMA 16x8x16 bf16 (baseline PTX, works on compute_103) ---
__device__ __forceinline__ void mma16816(float* d, const uint32_t* a, const uint32_t* b) {
    asm volatile(
        "mma.sync.aligned.m16n8k16.row.col.f32.bf16.bf16.f32 "
        "{%0,%1,%2,%3}, {%4,%5,%6,%7}, {%8,%9}, {%0,%1,%2,%3};"
        : "+f"(d[0]), "+f"(d[1]), "+f"(d[2]), "+f"(d[3])
        : "r"(a[0]), "r"(a[1]), "r"(a[2]), "r"(a[3]), "r"(b[0]), "r"(b[1]));
}

// ---------------- coalesced transpose + bf16 convert: [K,N] -> [NPAD,K] ----
template<int KD, int ND, int NPAD>
__global__ void k_tr(const float* __restrict__ W, __nv_bfloat16* __restrict__ out) {
    __shared__ float tile[32][33];
    int mIdx = blockIdx.z;
    const float* Wm = W + (long)mIdx * KD * ND;
    __nv_bfloat16* om = out + (long)mIdx * NPAD * KD;
    int n0 = blockIdx.x * 32, k0 = blockIdx.y * 32;
    int tx = threadIdx.x, ty = threadIdx.y;   // 32 x 8
#pragma unroll
    for (int i = 0; i < 32; i += 8) {
        int k = k0 + ty + i, n = n0 + tx;
        tile[ty + i][tx] = (k < KD && n < ND) ? Wm[(long)k * ND + n] : 0.f;
    }
    __syncthreads();
#pragma unroll
    for (int i = 0; i < 32; i += 8) {
        int n = n0 + ty + i, k = k0 + tx;
        if (n < NPAD && k < KD) om[(long)n * KD + k] = __float2bfloat16(tile[tx][ty + i]);
    }
}

// ---------------- x -> bf16 convert (gathers the 4 branch inputs) ----------
__global__ void k_xcvt(const float* __restrict__ x0, const float* __restrict__ x1,
                       const float* __restrict__ x2, const float* __restrict__ x3) {
    int gid = blockIdx.x * blockDim.x + threadIdx.x;      // one per 8 elems
    if (gid >= ROWS * DIN / 8) return;
    long e8 = (long)gid * 8;
    int nb = (int)(e8 / (RPB * DIN));
    long off = e8 - (long)nb * (RPB * DIN);
    const float* x = (nb == 0) ? x0 : (nb == 1) ? x1 : (nb == 2) ? x2 : x3;
    float4 a = *(const float4*)(x + off);
    float4 b = *(const float4*)(x + off + 4);
    __nv_bfloat162 o[4];
    o[0] = __floats2bfloat162_rn(a.x, a.y);
    o[1] = __floats2bfloat162_rn(a.z, a.w);
    o[2] = __floats2bfloat162_rn(b.x, b.y);
    o[3] = __floats2bfloat162_rn(b.z, b.w);
    *(uint4*)(g_xb + e8) = *(uint4*)o;
}

// ---------------- HMMA GEMM: C[M,N] = A[M,K] @ Bt[N,K]^T (batched over z) --
// MODE 1: f32 store cols<40   MODE 2: f32 + bf16   MODE 3: bf16 only
// MODE 4: column-sum reduce into g_poolp (no elementwise store)
template<int BM, int BN, int K, int MODE>
__global__ void __launch_bounds__(256, 1)
k_hmma(const __nv_bfloat16* __restrict__ A, const __nv_bfloat16* __restrict__ Bt,
       float* __restrict__ C, __nv_bfloat16* __restrict__ Cb,
       const float* __restrict__ bias, long biasStr,
       int Nld, long strA, long strB, long strC) {
    constexpr int LDK  = K + 8;
    constexpr int LDKU = LDK / 2;
    constexpr int WARPS_M = BM / 32;
    constexpr int WN = BN / (8 / WARPS_M);
    constexpr int NT = WN / 8;
    constexpr int K8 = K / 8;

    extern __shared__ __align__(16) char smem[];
    __nv_bfloat16* shA = (__nv_bfloat16*)smem;
    __nv_bfloat16* shB = shA + BM * LDK;

    int tid = threadIdx.x;
    int rowBase = blockIdx.y * BM;
    int colBase = blockIdx.x * BN;
    const __nv_bfloat16* Ap = A  + (long)blockIdx.z * strA + (long)rowBase * K;
    const __nv_bfloat16* Bp = Bt + (long)blockIdx.z * strB + (long)colBase * K;
    float* Cp = (MODE == 1 || MODE == 2) ? (C + (long)blockIdx.z * strC) : nullptr;
    __nv_bfloat16* Cbp = (MODE == 2 || MODE == 3) ? (Cb + (long)blockIdx.z * strC) : nullptr;
    const float* bp = bias ? (bias + (long)blockIdx.z * biasStr) : nullptr;

#pragma unroll 4
    for (int idx = tid; idx < BM * K8; idx += 256) {
        int r = idx / K8, c8 = idx - r * K8;
        *(uint4*)(shA + r * LDK + c8 * 8) = *(const uint4*)(Ap + (long)r * K + c8 * 8);
    }
#pragma unroll 4
    for (int idx = tid; idx < BN * K8; idx += 256) {
        int r = idx / K8, c8 = idx - r * K8;
        *(uint4*)(shB + r * LDK + c8 * 8) = *(const uint4*)(Bp + (long)r * K + c8 * 8);
    }
    __syncthreads();

    int w = tid >> 5, lane = tid & 31;
    int gid = lane >> 2, tig = lane & 3;
    int wm = w % WARPS_M, wn = w / WARPS_M;
    const uint32_t* sAu = (const uint32_t*)shA;
    const uint32_t* sBu = (const uint32_t*)shB;

    float acc[2][NT][4];
#pragma unroll
    for (int mt = 0; mt < 2; mt++)
#pragma unroll
        for (int nt = 0; nt < NT; nt++)
#pragma unroll
            for (int i = 0; i < 4; i++) acc[mt][nt][i] = 0.f;

    int aRow0 = wm * 32 + gid;
    int bRow0 = wn * WN + gid;

#pragma unroll
    for (int kt = 0; kt < K / 16; kt++) {
        int kb2 = kt * 8 + tig;
        uint32_t afr[2][4];
#pragma unroll
        for (int mt = 0; mt < 2; mt++) {
            int r0 = aRow0 + mt * 16;
            afr[mt][0] = sAu[r0 * LDKU + kb2];
            afr[mt][1] = sAu[(r0 + 8) * LDKU + kb2];
            afr[mt][2] = sAu[r0 * LDKU + kb2 + 4];
            afr[mt][3] = sAu[(r0 + 8) * LDKU + kb2 + 4];
        }
        uint32_t bfr[NT][2];
#pragma unroll
        for (int nt = 0; nt < NT; nt++) {
            int rb = bRow0 + nt * 8;
            bfr[nt][0] = sBu[rb * LDKU + kb2];
            bfr[nt][1] = sBu[rb * LDKU + kb2 + 4];
        }
#pragma unroll
        for (int mt = 0; mt < 2; mt++)
#pragma unroll
            for (int nt = 0; nt < NT; nt++)
                mma16816(acc[mt][nt], afr[mt], bfr[nt]);
    }

    if (MODE == 4) {
        // column sums over this block's BM rows -> pool partial (deterministic)
        __shared__ float s_col[BN];
#pragma unroll
        for (int nt = 0; nt < NT; nt++) {
            float v0 = acc[0][nt][0] + acc[0][nt][2] + acc[1][nt][0] + acc[1][nt][2];
            float v1 = acc[0][nt][1] + acc[0][nt][3] + acc[1][nt][1] + acc[1][nt][3];
#pragma unroll
            for (int o = 16; o >= 4; o >>= 1) {
                v0 += __shfl_xor_sync(0xffffffffu, v0, o);
                v1 += __shfl_xor_sync(0xffffffffu, v1, o);
            }
            acc[0][nt][0] = v0;   // reuse as stash
            acc[0][nt][1] = v1;
        }
        if (wm == 0 && gid == 0) {
#pragma unroll
            for (int nt = 0; nt < NT; nt++) {
                int c = wn * WN + nt * 8 + 2 * tig;
                s_col[c] = acc[0][nt][0];
                s_col[c + 1] = acc[0][nt][1];
            }
        }
        __syncthreads();
        if (wm == 1 && gid == 0) {
#pragma unroll
            for (int nt = 0; nt < NT; nt++) {
                int c = wn * WN + nt * 8 + 2 * tig;
                s_col[c] += acc[0][nt][0];
                s_col[c + 1] += acc[0][nt][1];
            }
        }
        __syncthreads();
        int y = blockIdx.y;
        int nbb = blockIdx.z * 4 + (y >> 4);
        int ck = y & 15;
        for (int i = tid; i < BN; i += 256)
            g_poolp[((nbb << 4) + ck) * DM + i] = s_col[i];
        return;
    }

#pragma unroll
    for (int mt = 0; mt < 2; mt++) {
#pragma unroll
        for (int nt = 0; nt < NT; nt++) {
            int r0 = rowBase + wm * 32 + mt * 16 + gid;
            int c0 = colBase + wn * WN + nt * 8 + 2 * tig;
            if (MODE == 1 && c0 >= 40) continue;
            float b0 = 0.f, b1 = 0.f;
            if (bp) { b0 = bp[c0]; b1 = bp[c0 + 1]; }
            float2 v0 = make_float2(acc[mt][nt][0] + b0, acc[mt][nt][1] + b1);
            float2 v1 = make_float2(acc[mt][nt][2] + b0, acc[mt][nt][3] + b1);
            if (MODE == 1 || MODE == 2) {
                *(float2*)(Cp + (long)r0 * Nld + c0) = v0;
                *(float2*)(Cp + (long)(r0 + 8) * Nld + c0) = v1;
            }
            if (MODE == 2 || MODE == 3) {
                *(__nv_bfloat162*)(Cbp + (long)r0 * Nld + c0) =
                    __floats2bfloat162_rn(v0.x, v0.y);
                *(__nv_bfloat162*)(Cbp + (long)(r0 + 8) * Nld + c0) =
                    __floats2bfloat162_rn(v1.x, v1.y);
            }
        }
    }
}

// ---------------- causal depthwise conv + SiLU (8 timesteps / thread) ------
__global__ void __launch_bounds__(256)
k_conv(const float* __restrict__ cw, const float* __restrict__ cb, int l) {
    int gid = blockIdx.x * blockDim.x + threadIdx.x;
    if (gid >= (ROWS / 8) * 64) return;
    int q  = gid & 63;
    int m8 = gid >> 6;
    int d0 = q * 4;
    int nb = m8 / (RPB / 8);
    int t0 = (m8 & (TT / 8 - 1)) * 8;
    int mrow = m8 * 8;

    const float* cwp = cw + (((long)(nb * NL + l)) * DI + d0) * DC;
    float cwa[16];
    *(float4*)(cwa + 0)  = *(const float4*)(cwp + 0);
    *(float4*)(cwa + 4)  = *(const float4*)(cwp + 4);
    *(float4*)(cwa + 8)  = *(const float4*)(cwp + 8);
    *(float4*)(cwa + 12) = *(const float4*)(cwp + 12);
    const float* cbp = cb + (long)(nb * NL + l) * DI + d0;
    float4 bias = *(const float4*)cbp;

    float4 xr[11];
#pragma unroll
    for (int j = 0; j < 11; j++) {
        int tr = t0 + j - 3;
        if (tr >= 0) {
            __nv_bfloat162 b01 = *(const __nv_bfloat162*)(g_xzb + (long)(mrow + j - 3) * (2 * DI) + d0);
            __nv_bfloat162 b23 = *(const __nv_bfloat162*)(g_xzb + (long)(mrow + j - 3) * (2 * DI) + d0 + 2);
            float2 f01 = __bfloat1622float2(b01);
            float2 f23 = __bfloat1622float2(b23);
            xr[j] = make_float4(f01.x, f01.y, f23.x, f23.y);
        } else {
            xr[j] = make_float4(0.f, 0.f, 0.f, 0.f);
        }
    }
#pragma unroll
    for (int i = 0; i < 8; i++) {
        float a0 = bias.x, a1 = bias.y, a2 = bias.z, a3 = bias.w;
#pragma unroll
        for (int k = 0; k < DC; k++) {
            float4 xv = xr[i + k];
            a0 = fmaf(xv.x, cwa[0 * DC + k], a0);
            a1 = fmaf(xv.y, cwa[1 * DC + k], a1);
            a2 = fmaf(xv.z, cwa[2 * DC + k], a2);
            a3 = fmaf(xv.w, cwa[3 * DC + k], a3);
        }
        long row = mrow + i;
        __nv_bfloat162* xb = (__nv_bfloat162*)(g_xcb + row * DI + d0);
        xb[0] = __floats2bfloat162_rn(siluf(a0), siluf(a1));
        xb[1] = __floats2bfloat162_rn(siluf(a2), siluf(a3));
    }
}

// ---------------- scan pass 1: fused dt + per-chunk local scan -------------
// P[s] = exp(a_s * sum_t dt_t)  (closed form, no per-step products)
__global__ void __launch_bounds__(256)
k_scan1(const float* __restrict__ Alog, const float* __restrict__ Wdt,
        const float* __restrict__ bdt, int l) {
    int c = blockIdx.x, nbb = blockIdx.y, d = threadIdx.x, nb = nbb >> 2;
    __shared__ float sD[CLEN][DTR];
    __shared__ float sB[CLEN][DS];
    int m0 = nbb * TT + c * CLEN;
    for (int i = d; i < CLEN * (DTR + DS); i += 256) {
        int r = i / (DTR + DS), j = i - r * (DTR + DS);
        float v = g_dbl[(long)(m0 + r) * DBLW + j];
        if (j < DTR) sD[r][j] = v; else sB[r][j - DTR] = v;
    }
    float a[DS];
    const float* Ap = Alog + ((long)(nb * NL + l) * DI + d) * DS;
#pragma unroll
    for (int s = 0; s < DS; s++) a[s] = -expf(Ap[s]);
    float A0 = a[0];
    bool ok = true;
#pragma unroll
    for (int s = 0; s < DS; s++)
        ok = ok && (fabsf(a[s] - (float)(s + 1) * A0) <= 1e-4f * fabsf(a[s]) + 1e-7f);
    float wdt[DTR];
    const float* wdp = Wdt + (long)(nb * NL + l) * DTR * DI + d;
#pragma unroll
    for (int r = 0; r < DTR; r++) wdt[r] = wdp[r * DI];
    float bdtv = bdt[(nb * NL + l) * DI + d];
    __syncthreads();

    float h[DS], Sdt = 0.f;
#pragma unroll
    for (int s = 0; s < DS; s++) h[s] = 0.f;
    if (ok) {
        for (int t = 0; t < CLEN; t++) {
            int mr = m0 + t;
            float u = bdtv;
#pragma unroll
            for (int r = 0; r < DTR; r++) u = fmaf(sD[t][r], wdt[r], u);
            float dtv = (u > 20.f) ? u : __logf(1.f + __expf(u));
            Sdt += dtv;
            float xcv = __bfloat162float(g_xcb[(long)mr * DI + d]);
            float w = dtv * xcv;
            float p = __expf(dtv * A0);
            float cum = 1.f;
#pragma unroll
            for (int s = 0; s < DS; s++) {
                cum *= p;
                h[s] = fmaf(cum, h[s], w * sB[t][s]);
            }
        }
    } else {
        for (int t = 0; t < CLEN; t++) {
            int mr = m0 + t;
            float u = bdtv;
#pragma unroll
            for (int r = 0; r < DTR; r++) u = fmaf(sD[t][r], wdt[r], u);
            float dtv = (u > 20.f) ? u : __logf(1.f + __expf(u));
            Sdt += dtv;
            float xcv = __bfloat162float(g_xcb[(long)mr * DI + d]);
            float w = dtv * xcv;
#pragma unroll
            for (int s = 0; s < DS; s++) {
                float dA = __expf(dtv * a[s]);
                h[s] = fmaf(dA, h[s], w * sB[t][s]);
            }
        }
    }
    long off = ((long)(c * NBB + nbb) * DI + d) * DS;
    float4* he = (float4*)(g_hend + off);
    float4* pe = (float4*)(g_P + off);
#pragma unroll
    for (int s4 = 0; s4 < 4; s4++) {
        he[s4] = make_float4(h[s4*4], h[s4*4+1], h[s4*4+2], h[s4*4+3]);
        pe[s4] = make_float4(__expf(a[s4*4] * Sdt),     __expf(a[s4*4+1] * Sdt),
                             __expf(a[s4*4+2] * Sdt),   __expf(a[s4*4+3] * Sdt));
    }
}

// ---------------- scan pass 2: combine carries across chunks ---------------
__global__ void k_carry() {
    int idx = blockIdx.x * blockDim.x + threadIdx.x;
    if (idx >= NBB * DI * DS) return;
    float h = 0.f;
#pragma unroll
    for (int c = 0; c < CHUNKS; c++) {
        long off = (long)c * (NBB * DI * DS) + idx;
        g_cry[off] = h;
        h = fmaf(g_P[off], h, g_hend[off]);
    }
}

// ---------------- scan pass 3: full scan + fused epilogue (bf16 ym) --------
__global__ void __launch_bounds__(256)
k_scan3(const float* __restrict__ Alog, const float* __restrict__ Wdt,
        const float* __restrict__ bdt, const float* __restrict__ Dpar, int l) {
    int c = blockIdx.x, nbb = blockIdx.y, d = threadIdx.x, nb = nbb >> 2;
    __shared__ float sD[CLEN][DTR];
    __shared__ float sB[CLEN][DS];
    __shared__ float sC[CLEN][DS];
    int m0 = nbb * TT + c * CLEN;
    for (int i = d; i < CLEN * DBLW; i += 256) {
        int r = i / DBLW, j = i - r * DBLW;
        float v = g_dbl[(long)(m0 + r) * DBLW + j];
        if (j < DTR) sD[r][j] = v;
        else if (j < DTR + DS) sB[r][j - DTR] = v;
        else sC[r][j - DTR - DS] = v;
    }
    float a[DS];
    const float* Ap = Alog + ((long)(nb * NL + l) * DI + d) * DS;
#pragma unroll
    for (int s = 0; s < DS; s++) a[s] = -expf(Ap[s]);
    float A0 = a[0];
    bool ok = true;
#pragma unroll
    for (int s = 0; s < DS; s++)
        ok = ok && (fabsf(a[s] - (float)(s + 1) * A0) <= 1e-4f * fabsf(a[s]) + 1e-7f);
    float wdt[DTR];
    const float* wdp = Wdt + (long)(nb * NL + l) * DTR * DI + d;
#pragma unroll
    for (int r = 0; r < DTR; r++) wdt[r] = wdp[r * DI];
    float bdtv = bdt[(nb * NL + l) * DI + d];
    float Dp = Dpar[(nb * NL + l) * DI + d];
    long off = ((long)(c * NBB + nbb) * DI + d) * DS;
    float h[DS];
#pragma unroll
    for (int s4 = 0; s4 < 4; s4++) {
        float4 cv = *(const float4*)(g_cry + off + s4 * 4);
        h[s4*4] = cv.x; h[s4*4+1] = cv.y; h[s4*4+2] = cv.z; h[s4*4+3] = cv.w;
    }
    __syncthreads();
    if (ok) {
        for (int t = 0; t < CLEN; t++) {
            int mr = m0 + t;
            float u = bdtv;
#pragma unroll
            for (int r = 0; r < DTR; r++) u = fmaf(sD[t][r], wdt[r], u);
            float dtv = (u > 20.f) ? u : __logf(1.f + __expf(u));
            float xcv = __bfloat162float(g_xcb[(long)mr * DI + d]);
            float w = dtv * xcv;
            float p = __expf(dtv * A0);
            float cum = 1.f, y = 0.f;
#pragma unroll
            for (int s = 0; s < DS; s++) {
                cum *= p;
                h[s] = fmaf(cum, h[s], w * sB[t][s]);
                y = fmaf(h[s], sC[t][s], y);
            }
            float yf = fmaf(Dp, xcv, y);
            float zv = __bfloat162float(g_xzb[(long)mr * (2 * DI) + DI + d]);
            g_ymb[(long)mr * DI + d] = __float2bfloat16(yf * siluf(zv));
        }
    } else {
        for (int t = 0; t < CLEN; t++) {
            int mr = m0 + t;
            float u = bdtv;
#pragma unroll
            for (int r = 0; r < DTR; r++) u = fmaf(sD[t][r], wdt[r], u);
            float dtv = (u > 20.f) ? u : __logf(1.f + __expf(u));
            float xcv = __bfloat162float(g_xcb[(long)mr * DI + d]);
            float w = dtv * xcv;
            float y = 0.f;
#pragma unroll
            for (int s = 0; s < DS; s++) {
                float dA = __expf(dtv * a[s]);
                h[s] = fmaf(dA, h[s], w * sB[t][s]);
                y = fmaf(h[s], sC[t][s], y);
            }
            float yf = fmaf(Dp, xcv, y);
            float zv = __bfloat162float(g_xzb[(long)mr * (2 * DI) + DI + d]);
            g_ymb[(long)mr * DI + d] = __float2bfloat16(yf * siluf(zv));
        }
    }
}

// ---------------- final: pool combine + output proj + Lorentz geometry -----
__global__ void __launch_bounds__(512)
k_final(const float* __restrict__ Wop, const float* __restrict__ bop,
        const float* __restrict__ eff, float* __restrict__ out) {
    __shared__ float s_pool[NBB][DM];
    __shared__ float s_us[NBB][EMB];
    int tid = threadIdx.x, w = tid >> 5, lane = tid & 31;
    int nb = w >> 2, b = w & 3;
    int c0 = lane, c1 = lane + 32;

    for (int idx = tid; idx < NBB * DM; idx += 512) {
        int p = idx >> 7, dm = idx & 127;
        float s = 0.f;
#pragma unroll
        for (int ch = 0; ch < 16; ch++) s += g_poolp[((p << 4) + ch) * DM + dm];
        s_pool[p][dm] = s * (1.f / (float)TT);
    }
    __syncthreads();

    float es = tanhf(eff[0]);
    float z0 = bop[nb * EMB + c0];
    float z1 = bop[nb * EMB + c1];
    const float* pl = s_pool[w];
    const float* wp = Wop + (long)nb * DM * EMB;
    for (int k = 0; k < DM; k++) {
        float pv = pl[k];
        z0 = fmaf(pv, wp[k * EMB + c0], z0);
        z1 = fmaf(pv, wp[k * EMB + c1], z1);
    }
    out[nb * (BB * EMB) + b * EMB + c0] = z0;
    out[nb * (BB * EMB) + b * EMB + c1] = z1;

    float v0 = z0 * es, v1 = z1 * es;
    float n2 = warpsum(v0 * v0 + v1 * v1);
    float n  = sqrtf(n2);
    float ncv = fminf(fmaxf(n, EPSV), MAXN);
    float sc  = ncv / fmaxf(n, EPSV);
    v0 *= sc; v1 *= sc;
    float shc = sinhf(ncv) / ncv;
    float sp0 = shc * v0, sp1 = shc * v1;
    float sp2 = warpsum(sp0 * sp0 + sp1 * sp1);
    float tproj = sqrtf(1.f + sp2);
    const int zhb = NBR * BB * EMB;
    float* oh = out + zhb + nb * (BB * 65) + b * 65;
    if (lane == 0) oh[0] = tproj;
    oh[1 + c0] = sp0;
    oh[1 + c1] = sp1;

    float ttv = fmaxf(tproj, 1.f + EPSV);
    float dd  = acoshf(ttv);
    float spn = fmaxf(sqrtf(sp2), EPSV);
    float rr  = dd / spn;
    s_us[w][c0] = rr * sp0;
    s_us[w][c1] = rr * sp1;
    __syncthreads();

    if (w < BB) {
        int b2 = w;
        float u0 = 0.f, u1 = 0.f;
#pragma unroll
        for (int q = 0; q < NBR; q++) {
            u0 += s_us[q * BB + b2][c0];
            u1 += s_us[q * BB + b2][c1];
        }
        const int ctb = zhb + NBR * BB * 65;
        out[ctb + b2 * EMB + c0] = u0;
        out[ctb + b2 * EMB + c1] = u1;
        float w0 = u0 * es, w1 = u1 * es;
        float m2 = warpsum(w0 * w0 + w1 * w1);
        float mn = sqrtf(m2);
        float mc = fminf(fmaxf(mn, EPSV), MAXN);
        float ms = mc / fmaxf(mn, EPSV);
        w0 *= ms; w1 *= ms;
        float msh = sinhf(mc) / mc;
        float q0 = msh * w0, q1 = msh * w1;
        float q2 = warpsum(q0 * q0 + q1 * q1);
        float t2 = sqrtf(1.f + q2);
        const int chb = ctb + BB * EMB;
        float* oc = out + chb + b2 * 65;
        if (lane == 0) oc[0] = t2;
        oc[1 + c0] = q0;
        oc[1 + c1] = q1;
    }
}

// ---------------------------------------------------------------------------
extern "C" void kernel_launch(void* const* d_in, const int* in_sizes, int n_in,
                              void* d_out, int out_size) {
    const float* x0   = (const float*)d_in[0];
    const float* x1   = (const float*)d_in[1];
    const float* x2   = (const float*)d_in[2];
    const float* x3   = (const float*)d_in[3];
    const float* Wip  = (const float*)d_in[4];
    const float* bip  = (const float*)d_in[5];
    const float* Win  = (const float*)d_in[6];
    const float* cw   = (const float*)d_in[7];
    const float* cb   = (const float*)d_in[8];
    const float* Wx   = (const float*)d_in[9];
    const float* Wdt  = (const float*)d_in[10];
    const float* bdt  = (const float*)d_in[11];
    const float* Alog = (const float*)d_in[12];
    const float* Dpar = (const float*)d_in[13];
    const float* Wout = (const float*)d_in[14];
    const float* Wop  = (const float*)d_in[15];
    const float* bop  = (const float*)d_in[16];
    const float* eff  = (const float*)d_in[17];
    float* out = (float*)d_out;

    __nv_bfloat16 *p_xb, *p_hb, *p_xzb, *p_xcb, *p_ymb;
    __nv_bfloat16 *p_WipT, *p_WinT, *p_WxT, *p_WoutT;
    float *p_dbl;
    cudaGetSymbolAddress((void**)&p_xb,    g_xb);
    cudaGetSymbolAddress((void**)&p_hb,    g_hb);
    cudaGetSymbolAddress((void**)&p_xzb,   g_xzb);
    cudaGetSymbolAddress((void**)&p_xcb,   g_xcb);
    cudaGetSymbolAddress((void**)&p_ymb,   g_ymb);
    cudaGetSymbolAddress((void**)&p_WipT,  g_WipT);
    cudaGetSymbolAddress((void**)&p_WinT,  g_WinT);
    cudaGetSymbolAddress((void**)&p_WxT,   g_WxT);
    cudaGetSymbolAddress((void**)&p_WoutT, g_WoutT);
    cudaGetSymbolAddress((void**)&p_dbl,   g_dbl);

    const int SM_G0 = (128 + 128) * (32 + 8) * 2;  // 20480
    const int SM_G1 = (128 + 128) * (128 + 8) * 2; // 69632
    const int SM_G2 = (64 + 64)   * (256 + 8) * 2; // 67584
    const int SM_G3 = (64 + 128)  * (256 + 8) * 2; // 101376
    cudaFuncSetAttribute(k_hmma<128,128,128,3>, cudaFuncAttributeMaxDynamicSharedMemorySize, SM_G1);
    cudaFuncSetAttribute(k_hmma<64,64,256,1>,   cudaFuncAttributeMaxDynamicSharedMemorySize, SM_G2);
    cudaFuncSetAttribute(k_hmma<64,128,256,3>,  cudaFuncAttributeMaxDynamicSharedMemorySize, SM_G3);
    cudaFuncSetAttribute(k_hmma<64,128,256,4>,  cudaFuncAttributeMaxDynamicSharedMemorySize, SM_G3);

    // weight transposes + input convert
    k_tr<32,  128, 128><<<dim3(4, 1, NBR),     dim3(32, 8)>>>(Wip,  p_WipT);
    k_tr<128, 512, 512><<<dim3(16, 4, NBR*NL), dim3(32, 8)>>>(Win,  p_WinT);
    k_tr<256, 40,  64 ><<<dim3(2,  8, NBR*NL), dim3(32, 8)>>>(Wx,   p_WxT);
    k_tr<256, 128, 128><<<dim3(4,  8, NBR*NL), dim3(32, 8)>>>(Wout, p_WoutT);
    k_xcvt<<<(ROWS * DIN / 8 + 255) / 256, 256>>>(x0, x1, x2, x3);

    // hb = bf16(x @ W_ip + b_ip)  via HMMA (K=32)
    k_hmma<128,128,32,3><<<dim3(1, RPB/128, NBR), 256, SM_G0>>>(
        p_xb, p_WipT, nullptr, p_hb, bip, DM,
        DM, (long)RPB*DIN, (long)DM*DIN, (long)RPB*DM);

    for (int l = 0; l < NL; l++) {
        // xz = h @ W_in[:,l]   (M=4096, N=512, K=128), bf16-only store
        k_hmma<128,128,128,3><<<dim3(4, RPB/128, NBR), 256, SM_G1>>>(
            p_hb, p_WinT + (long)l*512*128, nullptr, p_xzb, nullptr, 0,
            512, (long)RPB*128, (long)NL*512*128, (long)RPB*512);

        k_conv<<<((ROWS/8) * 64) / 256, 256>>>(cw, cb, l);

        // dbl = xc @ W_x[:,l]  (N=40 padded 64, K=256)
        k_hmma<64,64,256,1><<<dim3(1, RPB/64, NBR), 256, SM_G2>>>(
            p_xcb, p_WxT + (long)l*64*256, p_dbl, nullptr, nullptr, 0,
            DBLW, (long)RPB*256, (long)NL*64*256, (long)RPB*DBLW);

        k_scan1<<<dim3(CHUNKS, NBB), 256>>>(Alog, Wdt, bdt, l);
        k_carry<<<(NBB * DI * DS) / 256, 256>>>();
        k_scan3<<<dim3(CHUNKS, NBB), 256>>>(Alog, Wdt, bdt, Dpar, l);

        // h = ym @ W_out[:,l]  (N=128, K=256)
        if (l < NL - 1) {
            k_hmma<64,128,256,3><<<dim3(1, RPB/64, NBR), 256, SM_G3>>>(
                p_ymb, p_WoutT + (long)l*128*256, nullptr, p_hb, nullptr, 0,
                DM, (long)RPB*256, (long)NL*128*256, (long)RPB*DM);
        } else {
            // last layer: fuse mean-pool partial reduction into the GEMM
            k_hmma<64,128,256,4><<<dim3(1, RPB/64, NBR), 256, SM_G3>>>(
                p_ymb, p_WoutT + (long)l*128*256, nullptr, nullptr, nullptr, 0,
                DM, (long)RPB*256, (long)NL*128*256, (long)RPB*DM);
        }
    }

    k_final<<<1, 512>>>(Wop, bop, eff, out);
}

// round 14
// speedup vs baseline: 2.5375x; 1.0236x over previous
#include <cuda_runtime.h>
#include <cuda_bf16.h>
#include <math.h>
#include <stdint.h>

#define NBR 4
#define NL  3
#define BB  4
#define TT  1024
#define DIN 32
#define DM  128
#define DI  256
#define DS  16
#define DC  4
#define DTR 8
#define EMB 64
#define ROWS (NBR*BB*TT)   /* 16384 */
#define RPB  (BB*TT)       /* 4096  */
#define NBB  (NBR*BB)      /* 16    */
#define CHUNKS 32
#define CLEN (TT/CHUNKS)   /* 32    */
#define DBLW (DTR+2*DS)    /* 40    */
#define EPSV 1e-7f
#define MAXN 10.0f

// ---------------- scratch (static device memory; no allocs) ----------------
__device__ __nv_bfloat16  g_xb   [ROWS*DIN];
__device__ __nv_bfloat16  g_hb   [ROWS*DM];
__device__ __nv_bfloat16  g_xzb  [ROWS*2*DI];
__device__ __nv_bfloat16  g_xcb  [ROWS*DI];
__device__ float          g_dbl  [ROWS*DBLW];
__device__ __nv_bfloat16  g_ymb  [ROWS*DI];
__device__ float g_hend [CHUNKS*NBB*DI*DS];
__device__ float g_P    [CHUNKS*NBB*DI*DS];
__device__ float g_cry  [CHUNKS*NBB*DI*DS];
__device__ float g_poolp[NBB*16*DM];
// transposed bf16 weights: [br][l][N][K]
__device__ __nv_bfloat16 g_WipT [NBR*DM*DIN];
__device__ __nv_bfloat16 g_WinT [NBR*NL*512*128];
__device__ __nv_bfloat16 g_WxT  [NBR*NL*64*256];   // N padded 40->64 (zeros)
__device__ __nv_bfloat16 g_WoutT[NBR*NL*128*256];

__device__ __forceinline__ float warpsum(float v) {
#pragma unroll
    for (int o = 16; o > 0; o >>= 1) v += __shfl_xor_sync(0xffffffffu, v, o);
    return v;
}
__device__ __forceinline__ float siluf(float x) { return x / (1.f + __expf(-x)); }

// ---------------- HMMA 16x8x16 bf16 (baseline PTX, works on compute_103) ---
__device__ __forceinline__ void mma16816(float* d, const uint32_t* a, const uint32_t* b) {
    asm volatile(
        "mma.sync.aligned.m16n8k16.row.col.f32.bf16.bf16.f32 "
        "{%0,%1,%2,%3}, {%4,%5,%6,%7}, {%8,%9}, {%0,%1,%2,%3};"
        : "+f"(d[0]), "+f"(d[1]), "+f"(d[2]), "+f"(d[3])
        : "r"(a[0]), "r"(a[1]), "r"(a[2]), "r"(a[3]), "r"(b[0]), "r"(b[1]));
}

// ---------------- fused prep: all weight transposes + x -> bf16 ------------
// seg0 Wip(16) | seg1 Win(768) | seg2 Wx(192) | seg3 Wout(384) | seg4 xcvt(256)
__device__ void tr_tile(const float* __restrict__ W, __nv_bfloat16* __restrict__ out,
                        int KD, int ND, int NPAD, int nTile, int kTile,
                        float* tile, int tid) {
    int tx = tid & 31, ty = tid >> 5;
    int n0 = nTile * 32, k0 = kTile * 32;
#pragma unroll
    for (int i = 0; i < 32; i += 8) {
        int k = k0 + ty + i, n = n0 + tx;
        tile[(ty + i) * 33 + tx] = (k < KD && n < ND) ? W[(long)k * ND + n] : 0.f;
    }
    __syncthreads();
#pragma unroll
    for (int i = 0; i < 32; i += 8) {
        int n = n0 + ty + i, k = k0 + tx;
        if (n < NPAD && k < KD) out[(long)n * KD + k] = __float2bfloat16(tile[tx * 33 + ty + i]);
    }
}

__global__ void __launch_bounds__(256)
k_prep(const float* __restrict__ Wip, const float* __restrict__ Win,
       const float* __restrict__ Wx, const float* __restrict__ Wout,
       const float* __restrict__ x0, const float* __restrict__ x1,
       const float* __restrict__ x2, const float* __restrict__ x3) {
    __shared__ float tile[32 * 33];
    int bid = blockIdx.x, tid = threadIdx.x;
    if (bid < 16) {                 // Wip: KD=32, ND=128, nx=4, nk=1
        int local = bid;
        int m = local >> 2, rem = local & 3;
        tr_tile(Wip + (long)m * 32 * 128, g_WipT + (long)m * 128 * 32,
                32, 128, 128, rem, 0, tile, tid);
    } else if (bid < 784) {         // Win: KD=128, ND=512, nx=16, nk=4
        int local = bid - 16;
        int m = local / 64, rem = local % 64;
        int kT = rem / 16, nT = rem % 16;
        tr_tile(Win + (long)m * 128 * 512, g_WinT + (long)m * 512 * 128,
                128, 512, 512, nT, kT, tile, tid);
    } else if (bid < 976) {         // Wx: KD=256, ND=40->64, nx=2, nk=8
        int local = bid - 784;
        int m = local / 16, rem = local % 16;
        int kT = rem / 2, nT = rem % 2;
        tr_tile(Wx + (long)m * 256 * 40, g_WxT + (long)m * 64 * 256,
                256, 40, 64, nT, kT, tile, tid);
    } else if (bid < 1360) {        // Wout: KD=256, ND=128, nx=4, nk=8
        int local = bid - 976;
        int m = local / 32, rem = local % 32;
        int kT = rem / 4, nT = rem % 4;
        tr_tile(Wout + (long)m * 256 * 128, g_WoutT + (long)m * 128 * 256,
                256, 128, 128, nT, kT, tile, tid);
    } else {                        // xcvt: 256 blocks x 256 threads, 8 elems each
        int gid = (bid - 1360) * 256 + tid;
        long e8 = (long)gid * 8;
        int nb = (int)(e8 / (RPB * DIN));
        long off = e8 - (long)nb * (RPB * DIN);
        const float* x = (nb == 0) ? x0 : (nb == 1) ? x1 : (nb == 2) ? x2 : x3;
        float4 a = *(const float4*)(x + off);
        float4 b = *(const float4*)(x + off + 4);
        __nv_bfloat162 o[4];
        o[0] = __floats2bfloat162_rn(a.x, a.y);
        o[1] = __floats2bfloat162_rn(a.z, a.w);
        o[2] = __floats2bfloat162_rn(b.x, b.y);
        o[3] = __floats2bfloat162_rn(b.z, b.w);
        *(uint4*)(g_xb + e8) = *(uint4*)o;
    }
}

// ---------------- HMMA GEMM: C[M,N] = A[M,K] @ Bt[N,K]^T (batched over z) --
// MODE 3: bf16 only   MODE 4: column-sum reduce into g_poolp
template<int BM, int BN, int K, int MODE>
__global__ void __launch_bounds__(256, 1)
k_hmma(const __nv_bfloat16* __restrict__ A, const __nv_bfloat16* __restrict__ Bt,
       float* __restrict__ C, __nv_bfloat16* __restrict__ Cb,
       const float* __restrict__ bias, long biasStr,
       int Nld, long strA, long strB, long strC) {
    constexpr int LDK  = K + 8;
    constexpr int LDKU = LDK / 2;
    constexpr int WARPS_M = BM / 32;
    constexpr int WN = BN / (8 / WARPS_M);
    constexpr int NT = WN / 8;
    constexpr int K8 = K / 8;

    extern __shared__ __align__(16) char smem[];
    __nv_bfloat16* shA = (__nv_bfloat16*)smem;
    __nv_bfloat16* shB = shA + BM * LDK;

    int tid = threadIdx.x;
    int rowBase = blockIdx.y * BM;
    int colBase = blockIdx.x * BN;
    const __nv_bfloat16* Ap = A  + (long)blockIdx.z * strA + (long)rowBase * K;
    const __nv_bfloat16* Bp = Bt + (long)blockIdx.z * strB + (long)colBase * K;
    __nv_bfloat16* Cbp = (MODE == 3) ? (Cb + (long)blockIdx.z * strC) : nullptr;
    const float* bp = bias ? (bias + (long)blockIdx.z * biasStr) : nullptr;

#pragma unroll 4
    for (int idx = tid; idx < BM * K8; idx += 256) {
        int r = idx / K8, c8 = idx - r * K8;
        *(uint4*)(shA + r * LDK + c8 * 8) = *(const uint4*)(Ap + (long)r * K + c8 * 8);
    }
#pragma unroll 4
    for (int idx = tid; idx < BN * K8; idx += 256) {
        int r = idx / K8, c8 = idx - r * K8;
        *(uint4*)(shB + r * LDK + c8 * 8) = *(const uint4*)(Bp + (long)r * K + c8 * 8);
    }
    __syncthreads();

    int w = tid >> 5, lane = tid & 31;
    int gid = lane >> 2, tig = lane & 3;
    int wm = w % WARPS_M, wn = w / WARPS_M;
    const uint32_t* sAu = (const uint32_t*)shA;
    const uint32_t* sBu = (const uint32_t*)shB;

    float acc[2][NT][4];
#pragma unroll
    for (int mt = 0; mt < 2; mt++)
#pragma unroll
        for (int nt = 0; nt < NT; nt++)
#pragma unroll
            for (int i = 0; i < 4; i++) acc[mt][nt][i] = 0.f;

    int aRow0 = wm * 32 + gid;
    int bRow0 = wn * WN + gid;

#pragma unroll
    for (int kt = 0; kt < K / 16; kt++) {
        int kb2 = kt * 8 + tig;
        uint32_t afr[2][4];
#pragma unroll
        for (int mt = 0; mt < 2; mt++) {
            int r0 = aRow0 + mt * 16;
            afr[mt][0] = sAu[r0 * LDKU + kb2];
            afr[mt][1] = sAu[(r0 + 8) * LDKU + kb2];
            afr[mt][2] = sAu[r0 * LDKU + kb2 + 4];
            afr[mt][3] = sAu[(r0 + 8) * LDKU + kb2 + 4];
        }
        uint32_t bfr[NT][2];
#pragma unroll
        for (int nt = 0; nt < NT; nt++) {
            int rb = bRow0 + nt * 8;
            bfr[nt][0] = sBu[rb * LDKU + kb2];
            bfr[nt][1] = sBu[rb * LDKU + kb2 + 4];
        }
#pragma unroll
        for (int mt = 0; mt < 2; mt++)
#pragma unroll
            for (int nt = 0; nt < NT; nt++)
                mma16816(acc[mt][nt], afr[mt], bfr[nt]);
    }

    if (MODE == 4) {
        __shared__ float s_col[BN];
#pragma unroll
        for (int nt = 0; nt < NT; nt++) {
            float v0 = acc[0][nt][0] + acc[0][nt][2] + acc[1][nt][0] + acc[1][nt][2];
            float v1 = acc[0][nt][1] + acc[0][nt][3] + acc[1][nt][1] + acc[1][nt][3];
#pragma unroll
            for (int o = 16; o >= 4; o >>= 1) {
                v0 += __shfl_xor_sync(0xffffffffu, v0, o);
                v1 += __shfl_xor_sync(0xffffffffu, v1, o);
            }
            acc[0][nt][0] = v0;
            acc[0][nt][1] = v1;
        }
        if (wm == 0 && gid == 0) {
#pragma unroll
            for (int nt = 0; nt < NT; nt++) {
                int c = wn * WN + nt * 8 + 2 * tig;
                s_col[c] = acc[0][nt][0];
                s_col[c + 1] = acc[0][nt][1];
            }
        }
        __syncthreads();
        if (wm == 1 && gid == 0) {
#pragma unroll
            for (int nt = 0; nt < NT; nt++) {
                int c = wn * WN + nt * 8 + 2 * tig;
                s_col[c] += acc[0][nt][0];
                s_col[c + 1] += acc[0][nt][1];
            }
        }
        __syncthreads();
        int y = blockIdx.y;
        int nbb = blockIdx.z * 4 + (y >> 4);
        int ck = y & 15;
        for (int i = tid; i < BN; i += 256)
            g_poolp[((nbb << 4) + ck) * DM + i] = s_col[i];
        return;
    }

#pragma unroll
    for (int mt = 0; mt < 2; mt++) {
#pragma unroll
        for (int nt = 0; nt < NT; nt++) {
            int r0 = rowBase + wm * 32 + mt * 16 + gid;
            int c0 = colBase + wn * WN + nt * 8 + 2 * tig;
            float b0 = 0.f, b1 = 0.f;
            if (bp) { b0 = bp[c0]; b1 = bp[c0 + 1]; }
            float2 v0 = make_float2(acc[mt][nt][0] + b0, acc[mt][nt][1] + b1);
            float2 v1 = make_float2(acc[mt][nt][2] + b0, acc[mt][nt][3] + b1);
            *(__nv_bfloat162*)(Cbp + (long)r0 * Nld + c0) =
                __floats2bfloat162_rn(v0.x, v0.y);
            *(__nv_bfloat162*)(Cbp + (long)(r0 + 8) * Nld + c0) =
                __floats2bfloat162_rn(v1.x, v1.y);
        }
    }
}

// ---------------- fused conv + G2 GEMM: dbl = silu(conv(xz)) @ WxT^T --------
// BM=64, BN=64, K=256. Also writes g_xcb for the scans (identical bf16 values).
__global__ void __launch_bounds__(256, 1)
k_g2(const __nv_bfloat16* __restrict__ Bt, const float* __restrict__ cw,
     const float* __restrict__ cb, float* __restrict__ C, int l) {
    constexpr int K = 256, LDK = K + 8, LDKU = LDK / 2;
    constexpr int BM = 64, BN = 64, K8 = K / 8;
    constexpr int WN = 16, NT = 2;   // WARPS_M = 2

    extern __shared__ __align__(16) char smem[];
    __nv_bfloat16* shA   = (__nv_bfloat16*)smem;          // 64*264
    __nv_bfloat16* shB   = shA + BM * LDK;                // 64*264
    __nv_bfloat16* stage = shB + BM * LDK;                // 67*256

    int tid = threadIdx.x;
    int nb = blockIdx.z, y = blockIdx.y;
    int mrow = y * BM;
    long gRow = (long)nb * RPB + mrow;
    int t0 = mrow & (TT - 1);

    // stage fill: xz rows t0-3 .. t0+63 (first DI channels), zeros before t=0
    for (int i4 = tid; i4 < 67 * 32; i4 += 256) {
        int j = i4 >> 5, c16 = i4 & 31;
        uint4 v = make_uint4(0, 0, 0, 0);
        if (t0 - 3 + j >= 0)
            v = *(const uint4*)(g_xzb + (gRow + j - 3) * (2 * DI) + c16 * 8);
        *(uint4*)(stage + j * 256 + c16 * 8) = v;
    }
    // B fill
    const __nv_bfloat16* Bp = Bt + 0;
#pragma unroll 4
    for (int idx = tid; idx < BN * K8; idx += 256) {
        int r = idx / K8, c8 = idx - r * K8;
        *(uint4*)(shB + r * LDK + c8 * 8) = *(const uint4*)(Bp + (long)r * K + c8 * 8);
    }
    __syncthreads();

    // conv + silu -> shA (bf16) + g_xcb ; channels fixed per thread
    {
        int d0 = 2 * (tid & 127);
        int rhi = tid >> 7;
        const float* cwp = cw + (((long)(nb * NL + l)) * DI + d0) * DC;
        float cw0[4], cw1[4];
#pragma unroll
        for (int k = 0; k < 4; k++) { cw0[k] = cwp[k]; cw1[k] = cwp[4 + k]; }
        const float* cbp = cb + (long)(nb * NL + l) * DI + d0;
        float cb0 = cbp[0], cb1 = cbp[1];
#pragma unroll 4
        for (int i = 0; i < 32; i++) {
            int r = 2 * i + rhi;
            float u0 = cb0, u1 = cb1;
#pragma unroll
            for (int k = 0; k < 4; k++) {
                float2 xv = __bfloat1622float2(
                    *(const __nv_bfloat162*)(stage + (r + k) * 256 + d0));
                u0 = fmaf(xv.x, cw0[k], u0);
                u1 = fmaf(xv.y, cw1[k], u1);
            }
            __nv_bfloat162 o = __floats2bfloat162_rn(siluf(u0), siluf(u1));
            *(__nv_bfloat162*)(shA + r * LDK + d0) = o;
            *(__nv_bfloat162*)(g_xcb + (gRow + r) * DI + d0) = o;
        }
    }
    __syncthreads();

    int w = tid >> 5, lane = tid & 31;
    int gid = lane >> 2, tig = lane & 3;
    int wm = w & 1, wn = w >> 1;
    const uint32_t* sAu = (const uint32_t*)shA;
    const uint32_t* sBu = (const uint32_t*)shB;

    float acc[2][NT][4];
#pragma unroll
    for (int mt = 0; mt < 2; mt++)
#pragma unroll
        for (int nt = 0; nt < NT; nt++)
#pragma unroll
            for (int i = 0; i < 4; i++) acc[mt][nt][i] = 0.f;

    int aRow0 = wm * 32 + gid;
    int bRow0 = wn * WN + gid;

#pragma unroll
    for (int kt = 0; kt < K / 16; kt++) {
        int kb2 = kt * 8 + tig;
        uint32_t afr[2][4];
#pragma unroll
        for (int mt = 0; mt < 2; mt++) {
            int r0 = aRow0 + mt * 16;
            afr[mt][0] = sAu[r0 * LDKU + kb2];
            afr[mt][1] = sAu[(r0 + 8) * LDKU + kb2];
            afr[mt][2] = sAu[r0 * LDKU + kb2 + 4];
            afr[mt][3] = sAu[(r0 + 8) * LDKU + kb2 + 4];
        }
        uint32_t bfr[NT][2];
#pragma unroll
        for (int nt = 0; nt < NT; nt++) {
            int rb = bRow0 + nt * 8;
            bfr[nt][0] = sBu[rb * LDKU + kb2];
            bfr[nt][1] = sBu[rb * LDKU + kb2 + 4];
        }
#pragma unroll
        for (int mt = 0; mt < 2; mt++)
#pragma unroll
            for (int nt = 0; nt < NT; nt++)
                mma16816(acc[mt][nt], afr[mt], bfr[nt]);
    }

    float* Cp = C + (long)nb * ((long)RPB * DBLW);
#pragma unroll
    for (int mt = 0; mt < 2; mt++) {
#pragma unroll
        for (int nt = 0; nt < NT; nt++) {
            int r0 = mrow + wm * 32 + mt * 16 + gid;
            int c0 = wn * WN + nt * 8 + 2 * tig;
            if (c0 >= 40) continue;
            *(float2*)(Cp + (long)r0 * DBLW + c0) =
                make_float2(acc[mt][nt][0], acc[mt][nt][1]);
            *(float2*)(Cp + (long)(r0 + 8) * DBLW + c0) =
                make_float2(acc[mt][nt][2], acc[mt][nt][3]);
        }
    }
}

// ---------------- scan pass 1: fused dt + per-chunk local scan -------------
__global__ void __launch_bounds__(256)
k_scan1(const float* __restrict__ Alog, const float* __restrict__ Wdt,
        const float* __restrict__ bdt, int l) {
    int c = blockIdx.x, nbb = blockIdx.y, d = threadIdx.x, nb = nbb >> 2;
    __shared__ float sD[CLEN][DTR];
    __shared__ float sB[CLEN][DS];
    int m0 = nbb * TT + c * CLEN;
    for (int i = d; i < CLEN * (DTR + DS); i += 256) {
        int r = i / (DTR + DS), j = i - r * (DTR + DS);
        float v = g_dbl[(long)(m0 + r) * DBLW + j];
        if (j < DTR) sD[r][j] = v; else sB[r][j - DTR] = v;
    }
    float a[DS];
    const float* Ap = Alog + ((long)(nb * NL + l) * DI + d) * DS;
#pragma unroll
    for (int s = 0; s < DS; s++) a[s] = -expf(Ap[s]);
    float A0 = a[0];
    bool ok = true;
#pragma unroll
    for (int s = 0; s < DS; s++)
        ok = ok && (fabsf(a[s] - (float)(s + 1) * A0) <= 1e-4f * fabsf(a[s]) + 1e-7f);
    float wdt[DTR];
    const float* wdp = Wdt + (long)(nb * NL + l) * DTR * DI + d;
#pragma unroll
    for (int r = 0; r < DTR; r++) wdt[r] = wdp[r * DI];
    float bdtv = bdt[(nb * NL + l) * DI + d];
    __syncthreads();

    float h[DS], Sdt = 0.f;
#pragma unroll
    for (int s = 0; s < DS; s++) h[s] = 0.f;
    if (ok) {
        for (int t = 0; t < CLEN; t++) {
            int mr = m0 + t;
            float u = bdtv;
#pragma unroll
            for (int r = 0; r < DTR; r++) u = fmaf(sD[t][r], wdt[r], u);
            float dtv = (u > 20.f) ? u : __logf(1.f + __expf(u));
            Sdt += dtv;
            float xcv = __bfloat162float(g_xcb[(long)mr * DI + d]);
            float w = dtv * xcv;
            float p = __expf(dtv * A0);
            float cum = 1.f;
#pragma unroll
            for (int s = 0; s < DS; s++) {
                cum *= p;
                h[s] = fmaf(cum, h[s], w * sB[t][s]);
            }
        }
    } else {
        for (int t = 0; t < CLEN; t++) {
            int mr = m0 + t;
            float u = bdtv;
#pragma unroll
            for (int r = 0; r < DTR; r++) u = fmaf(sD[t][r], wdt[r], u);
            float dtv = (u > 20.f) ? u : __logf(1.f + __expf(u));
            Sdt += dtv;
            float xcv = __bfloat162float(g_xcb[(long)mr * DI + d]);
            float w = dtv * xcv;
#pragma unroll
            for (int s = 0; s < DS; s++) {
                float dA = __expf(dtv * a[s]);
                h[s] = fmaf(dA, h[s], w * sB[t][s]);
            }
        }
    }
    long off = ((long)(c * NBB + nbb) * DI + d) * DS;
    float4* he = (float4*)(g_hend + off);
    float4* pe = (float4*)(g_P + off);
#pragma unroll
    for (int s4 = 0; s4 < 4; s4++) {
        he[s4] = make_float4(h[s4*4], h[s4*4+1], h[s4*4+2], h[s4*4+3]);
        pe[s4] = make_float4(__expf(a[s4*4] * Sdt),   __expf(a[s4*4+1] * Sdt),
                             __expf(a[s4*4+2] * Sdt), __expf(a[s4*4+3] * Sdt));
    }
}

// ---------------- scan pass 2: combine carries across chunks ---------------
__global__ void k_carry() {
    int idx = blockIdx.x * blockDim.x + threadIdx.x;
    if (idx >= NBB * DI * DS) return;
    float h = 0.f;
#pragma unroll
    for (int c = 0; c < CHUNKS; c++) {
        long off = (long)c * (NBB * DI * DS) + idx;
        g_cry[off] = h;
        h = fmaf(g_P[off], h, g_hend[off]);
    }
}

// ---------------- scan pass 3: full scan + fused epilogue (bf16 ym) --------
__global__ void __launch_bounds__(256)
k_scan3(const float* __restrict__ Alog, const float* __restrict__ Wdt,
        const float* __restrict__ bdt, const float* __restrict__ Dpar, int l) {
    int c = blockIdx.x, nbb = blockIdx.y, d = threadIdx.x, nb = nbb >> 2;
    __shared__ float sD[CLEN][DTR];
    __shared__ float sB[CLEN][DS];
    __shared__ float sC[CLEN][DS];
    int m0 = nbb * TT + c * CLEN;
    for (int i = d; i < CLEN * DBLW; i += 256) {
        int r = i / DBLW, j = i - r * DBLW;
        float v = g_dbl[(long)(m0 + r) * DBLW + j];
        if (j < DTR) sD[r][j] = v;
        else if (j < DTR + DS) sB[r][j - DTR] = v;
        else sC[r][j - DTR - DS] = v;
    }
    float a[DS];
    const float* Ap = Alog + ((long)(nb * NL + l) * DI + d) * DS;
#pragma unroll
    for (int s = 0; s < DS; s++) a[s] = -expf(Ap[s]);
    float A0 = a[0];
    bool ok = true;
#pragma unroll
    for (int s = 0; s < DS; s++)
        ok = ok && (fabsf(a[s] - (float)(s + 1) * A0) <= 1e-4f * fabsf(a[s]) + 1e-7f);
    float wdt[DTR];
    const float* wdp = Wdt + (long)(nb * NL + l) * DTR * DI + d;
#pragma unroll
    for (int r = 0; r < DTR; r++) wdt[r] = wdp[r * DI];
    float bdtv = bdt[(nb * NL + l) * DI + d];
    float Dp = Dpar[(nb * NL + l) * DI + d];
    long off = ((long)(c * NBB + nbb) * DI + d) * DS;
    float h[DS];
#pragma unroll
    for (int s4 = 0; s4 < 4; s4++) {
        float4 cv = *(const float4*)(g_cry + off + s4 * 4);
        h[s4*4] = cv.x; h[s4*4+1] = cv.y; h[s4*4+2] = cv.z; h[s4*4+3] = cv.w;
    }
    __syncthreads();
    if (ok) {
        for (int t = 0; t < CLEN; t++) {
            int mr = m0 + t;
            float u = bdtv;
#pragma unroll
            for (int r = 0; r < DTR; r++) u = fmaf(sD[t][r], wdt[r], u);
            float dtv = (u > 20.f) ? u : __logf(1.f + __expf(u));
            float xcv = __bfloat162float(g_xcb[(long)mr * DI + d]);
            float w = dtv * xcv;
            float p = __expf(dtv * A0);
            float cum = 1.f, y = 0.f;
#pragma unroll
            for (int s = 0; s < DS; s++) {
                cum *= p;
                h[s] = fmaf(cum, h[s], w * sB[t][s]);
                y = fmaf(h[s], sC[t][s], y);
            }
            float yf = fmaf(Dp, xcv, y);
            float zv = __bfloat162float(g_xzb[(long)mr * (2 * DI) + DI + d]);
            g_ymb[(long)mr * DI + d] = __float2bfloat16(yf * siluf(zv));
        }
    } else {
        for (int t = 0; t < CLEN; t++) {
            int mr = m0 + t;
            float u = bdtv;
#pragma unroll
            for (int r = 0; r < DTR; r++) u = fmaf(sD[t][r], wdt[r], u);
            float dtv = (u > 20.f) ? u : __logf(1.f + __expf(u));
            float xcv = __bfloat162float(g_xcb[(long)mr * DI + d]);
            float w = dtv * xcv;
            float y = 0.f;
#pragma unroll
            for (int s = 0; s < DS; s++) {
                float dA = __expf(dtv * a[s]);
                h[s] = fmaf(dA, h[s], w * sB[t][s]);
                y = fmaf(h[s], sC[t][s], y);
            }
            float yf = fmaf(Dp, xcv, y);
            float zv = __bfloat162float(g_xzb[(long)mr * (2 * DI) + DI + d]);
            g_ymb[(long)mr * DI + d] = __float2bfloat16(yf * siluf(zv));
        }
    }
}

// ---------------- final: pool combine + output proj + Lorentz geometry -----
__global__ void __launch_bounds__(512)
k_final(const float* __restrict__ Wop, const float* __restrict__ bop,
        const float* __restrict__ eff, float* __restrict__ out) {
    __shared__ float s_pool[NBB][DM];
    __shared__ float s_us[NBB][EMB];
    int tid = threadIdx.x, w = tid >> 5, lane = tid & 31;
    int nb = w >> 2, b = w & 3;
    int c0 = lane, c1 = lane + 32;

    for (int idx = tid; idx < NBB * DM; idx += 512) {
        int p = idx >> 7, dm = idx & 127;
        float s = 0.f;
#pragma unroll
        for (int ch = 0; ch < 16; ch++) s += g_poolp[((p << 4) + ch) * DM + dm];
        s_pool[p][dm] = s * (1.f / (float)TT);
    }
    __syncthreads();

    float es = tanhf(eff[0]);
    float z0 = bop[nb * EMB + c0];
    float z1 = bop[nb * EMB + c1];
    const float* pl = s_pool[w];
    const float* wp = Wop + (long)nb * DM * EMB;
    for (int k = 0; k < DM; k++) {
        float pv = pl[k];
        z0 = fmaf(pv, wp[k * EMB + c0], z0);
        z1 = fmaf(pv, wp[k * EMB + c1], z1);
    }
    out[nb * (BB * EMB) + b * EMB + c0] = z0;
    out[nb * (BB * EMB) + b * EMB + c1] = z1;

    float v0 = z0 * es, v1 = z1 * es;
    float n2 = warpsum(v0 * v0 + v1 * v1);
    float n  = sqrtf(n2);
    float ncv = fminf(fmaxf(n, EPSV), MAXN);
    float sc  = ncv / fmaxf(n, EPSV);
    v0 *= sc; v1 *= sc;
    float shc = sinhf(ncv) / ncv;
    float sp0 = shc * v0, sp1 = shc * v1;
    float sp2 = warpsum(sp0 * sp0 + sp1 * sp1);
    float tproj = sqrtf(1.f + sp2);
    const int zhb = NBR * BB * EMB;
    float* oh = out + zhb + nb * (BB * 65) + b * 65;
    if (lane == 0) oh[0] = tproj;
    oh[1 + c0] = sp0;
    oh[1 + c1] = sp1;

    float ttv = fmaxf(tproj, 1.f + EPSV);
    float dd  = acoshf(ttv);
    float spn = fmaxf(sqrtf(sp2), EPSV);
    float rr  = dd / spn;
    s_us[w][c0] = rr * sp0;
    s_us[w][c1] = rr * sp1;
    __syncthreads();

    if (w < BB) {
        int b2 = w;
        float u0 = 0.f, u1 = 0.f;
#pragma unroll
        for (int q = 0; q < NBR; q++) {
            u0 += s_us[q * BB + b2][c0];
            u1 += s_us[q * BB + b2][c1];
        }
        const int ctb = zhb + NBR * BB * 65;
        out[ctb + b2 * EMB + c0] = u0;
        out[ctb + b2 * EMB + c1] = u1;
        float w0 = u0 * es, w1 = u1 * es;
        float m2 = warpsum(w0 * w0 + w1 * w1);
        float mn = sqrtf(m2);
        float mc = fminf(fmaxf(mn, EPSV), MAXN);
        float ms = mc / fmaxf(mn, EPSV);
        w0 *= ms; w1 *= ms;
        float msh = sinhf(mc) / mc;
        float q0 = msh * w0, q1 = msh * w1;
        float q2 = warpsum(q0 * q0 + q1 * q1);
        float t2 = sqrtf(1.f + q2);
        const int chb = ctb + BB * EMB;
        float* oc = out + chb + b2 * 65;
        if (lane == 0) oc[0] = t2;
        oc[1 + c0] = q0;
        oc[1 + c1] = q1;
    }
}

// ---------------------------------------------------------------------------
extern "C" void kernel_launch(void* const* d_in, const int* in_sizes, int n_in,
                              void* d_out, int out_size) {
    const float* x0   = (const float*)d_in[0];
    const float* x1   = (const float*)d_in[1];
    const float* x2   = (const float*)d_in[2];
    const float* x3   = (const float*)d_in[3];
    const float* Wip  = (const float*)d_in[4];
    const float* bip  = (const float*)d_in[5];
    const float* Win  = (const float*)d_in[6];
    const float* cw   = (const float*)d_in[7];
    const float* cb   = (const float*)d_in[8];
    const float* Wx   = (const float*)d_in[9];
    const float* Wdt  = (const float*)d_in[10];
    const float* bdt  = (const float*)d_in[11];
    const float* Alog = (const float*)d_in[12];
    const float* Dpar = (const float*)d_in[13];
    const float* Wout = (const float*)d_in[14];
    const float* Wop  = (const float*)d_in[15];
    const float* bop  = (const float*)d_in[16];
    const float* eff  = (const float*)d_in[17];
    float* out = (float*)d_out;

    __nv_bfloat16 *p_xb, *p_hb, *p_xzb, *p_ymb;
    __nv_bfloat16 *p_WipT, *p_WinT, *p_WxT, *p_WoutT;
    float *p_dbl;
    cudaGetSymbolAddress((void**)&p_xb,    g_xb);
    cudaGetSymbolAddress((void**)&p_hb,    g_hb);
    cudaGetSymbolAddress((void**)&p_xzb,   g_xzb);
    cudaGetSymbolAddress((void**)&p_ymb,   g_ymb);
    cudaGetSymbolAddress((void**)&p_WipT,  g_WipT);
    cudaGetSymbolAddress((void**)&p_WinT,  g_WinT);
    cudaGetSymbolAddress((void**)&p_WxT,   g_WxT);
    cudaGetSymbolAddress((void**)&p_WoutT, g_WoutT);
    cudaGetSymbolAddress((void**)&p_dbl,   g_dbl);

    const int SM_G0 = (128 + 128) * (32 + 8) * 2;   // 20480
    const int SM_G1 = (128 + 128) * (128 + 8) * 2;  // 69632
    const int SM_G2 = 2 * 64 * (256 + 8) * 2 + 67 * 256 * 2; // 101888
    const int SM_G3 = (64 + 128)  * (256 + 8) * 2;  // 101376
    cudaFuncSetAttribute(k_hmma<128,128,128,3>, cudaFuncAttributeMaxDynamicSharedMemorySize, SM_G1);
    cudaFuncSetAttribute(k_g2,                  cudaFuncAttributeMaxDynamicSharedMemorySize, SM_G2);
    cudaFuncSetAttribute(k_hmma<64,128,256,3>,  cudaFuncAttributeMaxDynamicSharedMemorySize, SM_G3);
    cudaFuncSetAttribute(k_hmma<64,128,256,4>,  cudaFuncAttributeMaxDynamicSharedMemorySize, SM_G3);

    // fused prep: all weight transposes + x -> bf16
    k_prep<<<1616, 256>>>(Wip, Win, Wx, Wout, x0, x1, x2, x3);

    // hb = bf16(x @ W_ip + b_ip)  via HMMA (K=32)
    k_hmma<128,128,32,3><<<dim3(1, RPB/128, NBR), 256, SM_G0>>>(
        p_xb, p_WipT, nullptr, p_hb, bip, DM,
        DM, (long)RPB*DIN, (long)DM*DIN, (long)RPB*DM);

    for (int l = 0; l < NL; l++) {
        // xz = h @ W_in[:,l]   (M=4096, N=512, K=128), bf16-only store
        k_hmma<128,128,128,3><<<dim3(4, RPB/128, NBR), 256, SM_G1>>>(
            p_hb, p_WinT + (long)l*512*128, nullptr, p_xzb, nullptr, 0,
            512, (long)RPB*128, (long)NL*512*128, (long)RPB*512);

        // fused conv+SiLU+GEMM: dbl = xc @ W_x[:,l], also writes g_xcb
        k_g2<<<dim3(1, RPB/64, NBR), 256, SM_G2>>>(
            p_WxT + (long)l*64*256, cw, cb, p_dbl, l);

        k_scan1<<<dim3(CHUNKS, NBB), 256>>>(Alog, Wdt, bdt, l);
        k_carry<<<(NBB * DI * DS) / 256, 256>>>();
        k_scan3<<<dim3(CHUNKS, NBB), 256>>>(Alog, Wdt, bdt, Dpar, l);

        // h = ym @ W_out[:,l]  (N=128, K=256)
        if (l < NL - 1) {
            k_hmma<64,128,256,3><<<dim3(1, RPB/64, NBR), 256, SM_G3>>>(
                p_ymb, p_WoutT + (long)l*128*256, nullptr, p_hb, nullptr, 0,
                DM, (long)RPB*256, (long)NL*128*256, (long)RPB*DM);
        } else {
            k_hmma<64,128,256,4><<<dim3(1, RPB/64, NBR), 256, SM_G3>>>(
                p_ymb, p_WoutT + (long)l*128*256, nullptr, nullptr, nullptr, 0,
                DM, (long)RPB*256, (long)NL*128*256, (long)RPB*DM);
        }
    }

    k_final<<<1, 512>>>(Wop, bop, eff, out);
}